// round 12
// baseline (speedup 1.0000x reference)
#include <cuda_runtime.h>
#include <cstdint>

// ---------------------------------------------------------------------------
// Problem constants
// ---------------------------------------------------------------------------
#define NLEV 5
#define BATCH 4
#define PRE_NMS 2000
#define POST_NMS 1000
#define NBL (BATCH * NLEV)          // 20 (batch, level) pairs
#define SORT_CAP 4096               // max bitonic capacity
#define TOTCAT 4768                 // 4*1000 + 768 concatenated entries
#define HBINS 65536
#define NTILE 32                    // 2000/64 -> 32 tiles
#define NTRI  528                   // 32*33/2 upper-triangle tile pairs
#define HBLOCKS 16                  // hist blocks per bl
#define MBLOCKS 33                  // mask blocks per bl (33*16 groups = 528)

__constant__ int c_A[NLEV]      = {196608, 49152, 12288, 3072, 768};
__constant__ int c_K[NLEV]      = {2000, 2000, 2000, 2000, 768};
__constant__ int c_KP[NLEV]     = {1000, 1000, 1000, 1000, 768};
__constant__ int c_stride[NLEV] = {4, 8, 16, 32, 64};
__constant__ int c_grid[NLEV]   = {256, 128, 64, 32, 16};
__constant__ int c_base[NLEV]   = {32, 64, 128, 256, 512};

// ---------------------------------------------------------------------------
// Device scratch (static allocation only; __device__ globals are zero-init)
// ---------------------------------------------------------------------------
__device__ int                 d_hist   [NBL * HBINS];      // kept zeroed by winners
__device__ unsigned            d_T      [NBL];
__device__ int                 d_cnt    [NBL];
__device__ unsigned            d_done1  [NBL];              // monotone arrival ctr
__device__ unsigned            d_done2  [NBL];              // monotone arrival ctr
__device__ unsigned long long  d_cand   [NBL * SORT_CAP];
__device__ int                 d_topIdx [NBL * PRE_NMS];
__device__ float               d_topScore[NBL * PRE_NMS];
__device__ float4              d_topBoxes[NBL * PRE_NMS];
__device__ unsigned long long  d_maskT  [NBL * 32 * PRE_NMS];   // [(bl*32+col)*2000+row]
__device__ float               d_lvlScore[NBL * POST_NMS];
__device__ int                 d_lvlPos  [NBL * POST_NMS];

// ---------------------------------------------------------------------------
// Helpers
// ---------------------------------------------------------------------------
__device__ __forceinline__ unsigned ordf(float f) {
    unsigned u = __float_as_uint(f);
    return (u & 0x80000000u) ? ~u : (u | 0x80000000u);
}
__device__ __forceinline__ float iordf(unsigned u) {
    unsigned v = (u & 0x80000000u) ? (u & 0x7FFFFFFFu) : ~u;
    return __uint_as_float(v);
}
__device__ __forceinline__ const float* pick(const float* a0, const float* a1,
                                             const float* a2, const float* a3,
                                             const float* a4, int l) {
    switch (l) { case 0: return a0; case 1: return a1; case 2: return a2;
                 case 3: return a3; default: return a4; }
}
// Warp-aggregated append; all 32 lanes must execute (use padded loops).
__device__ __forceinline__ int warpAppend(int* ctr, bool pred) {
    unsigned m = __ballot_sync(0xffffffffu, pred);
    int lane = threadIdx.x & 31;
    int base = 0;
    if (m != 0) {
        int leader = __ffs(m) - 1;
        if (lane == leader) base = atomicAdd(ctr, __popc(m));
        base = __shfl_sync(0xffffffffu, base, leader);
    }
    return pred ? base + __popc(m & ((1u << lane) - 1u)) : -1;
}

// ---------------------------------------------------------------------------
// Kernel 1: histogram + (last block per bl) threshold select.
// grid (HBLOCKS, NBL) x 1024. Winner copy-zeroes its bins so d_hist stays
// zeroed for the next launch (no memset node). Monotone counter: winner is
// arrival with old % HBLOCKS == HBLOCKS-1 — replay-safe.
// ---------------------------------------------------------------------------
__global__ __launch_bounds__(1024)
void hist_select_kernel(const float* __restrict__ p0, const float* __restrict__ p1,
                        const float* __restrict__ p2, const float* __restrict__ p3,
                        const float* __restrict__ p4) {
    const int bl = blockIdx.y;
    const int b = bl / NLEV, l = bl % NLEV;
    const int A = c_A[l];
    const int K = c_K[l];
    const float2* base2 = (const float2*)(pick(p0, p1, p2, p3, p4, l) + (size_t)b * A * 2);
    int* hist = d_hist + (size_t)bl * HBINS;
    const int tid = threadIdx.x;

    __shared__ int sA[1024], sB[1024];
    __shared__ int s_win;

    // ---- histogram over my chunk ----
    const int chunk = (A + HBLOCKS - 1) / HBLOCKS;
    const int start = blockIdx.x * chunk;
    const int end = min(start + chunk, A);
    for (int i = start + tid; i < end; i += 1024)
        atomicAdd(&hist[ordf(base2[i].x) >> 16], 1);

    // ---- arrive; last block does select ----
    __threadfence();
    __syncthreads();
    if (tid == 0) {
        unsigned old = atomicAdd(&d_done1[bl], 1u);
        s_win = ((old % HBLOCKS) == (HBLOCKS - 1)) ? 1 : 0;
    }
    __syncthreads();
    if (!s_win) return;
    __threadfence();                     // acquire: see all blocks' hist adds

    if (tid == 0) d_cnt[bl] = 0;

    // thread t owns 64 bins [hi-63, hi], hi = 65535 - 64*t (descending order)
    const int hi = HBINS - 1 - (tid << 6);
    int localbin[64];
    int sum = 0;
    #pragma unroll 8
    for (int k = 0; k < 64; ++k) {
        localbin[k] = hist[hi - k];
        sum += localbin[k];
        hist[hi - k] = 0;                // restore zero-invariant for next launch
    }
    sA[tid] = sum;
    __syncthreads();

    int* src = sA; int* dst = sB;
    for (int off = 1; off < 1024; off <<= 1) {
        dst[tid] = src[tid] + ((tid >= off) ? src[tid - off] : 0);
        __syncthreads();
        int* t2 = src; src = dst; dst = t2;
    }

    const int prev = (tid == 0) ? 0 : src[tid - 1];
    if (src[tid] >= K && prev < K) {
        int cum = prev;
        unsigned Tb = 0;
        for (int k = 0; k < 64; ++k) {
            cum += localbin[k];
            if (cum >= K) { Tb = (unsigned)(hi - k); break; }
        }
        d_T[bl] = Tb << 16;
    }
}

// ---------------------------------------------------------------------------
// Kernel 2: parallel compaction of u >= T into per-bl candidate list.
// ---------------------------------------------------------------------------
__global__ __launch_bounds__(256)
void compact_kernel(const float* __restrict__ p0, const float* __restrict__ p1,
                    const float* __restrict__ p2, const float* __restrict__ p3,
                    const float* __restrict__ p4) {
    const int bl = blockIdx.y;
    const int b = bl / NLEV, l = bl % NLEV;
    const int A = c_A[l];
    const float2* base2 = (const float2*)(pick(p0, p1, p2, p3, p4, l) + (size_t)b * A * 2);
    const unsigned T = d_T[bl];
    unsigned long long* cand = d_cand + (size_t)bl * SORT_CAP;
    const int lane = threadIdx.x & 31;

    const int chunk = (A + 63) >> 6;
    const int start = blockIdx.x * chunk;
    const int end = min(start + chunk, A);
    const int n = end - start;
    const int rounds = (n + 255) >> 8;
    for (int r = 0; r < rounds; ++r) {
        int i = start + threadIdx.x + (r << 8);
        bool in = i < end;
        unsigned u = 0;
        if (in) u = ordf(base2[i].x);
        bool take = in && (u >= T);
        unsigned m = __ballot_sync(0xffffffffu, take);
        if (m) {
            int leader = __ffs(m) - 1;
            int basep = 0;
            if (lane == leader) basep = atomicAdd(&d_cnt[bl], __popc(m));
            basep = __shfl_sync(0xffffffffu, basep, leader);
            if (take) {
                int p = basep + __popc(m & ((1u << lane) - 1u));
                if (p < SORT_CAP)
                    cand[p] = ((unsigned long long)u << 32) | (unsigned)(~i);
            }
        }
    }
}

// ---------------------------------------------------------------------------
// Kernel 3: per-bl threshold REFINEMENT (24-bit) + bitonic sort + decode.
// ---------------------------------------------------------------------------
__global__ __launch_bounds__(1024)
void sort_decode_kernel(const float* __restrict__ r0, const float* __restrict__ r1,
                        const float* __restrict__ r2, const float* __restrict__ r3,
                        const float* __restrict__ r4, const float* __restrict__ info) {
    const int bl = blockIdx.x;
    const int b = bl / NLEV, l = bl % NLEV;
    const int K = c_K[l];
    const int tid = threadIdx.x;
    const int lane = tid & 31;

    __shared__ unsigned long long cand[SORT_CAP];   // 32 KB
    __shared__ int h256[256];
    __shared__ int s_c0, s_b2, s_cnt2;
    __shared__ float s_aw[3], s_ah[3];

    if (tid < 3) {
        double rr = (tid == 0) ? 0.5 : ((tid == 1) ? 1.0 : 2.0);
        double sb = (double)c_base[l] * 8.0;
        s_aw[tid] = (float)(sb * sqrt(1.0 / rr));
        s_ah[tid] = (float)(sb * sqrt(rr));
    }

    const unsigned long long* gc = d_cand + (size_t)bl * SORT_CAP;
    const int M = min(d_cnt[bl], SORT_CAP);

    // ---- Refine threshold to 24 bits when the coarse set exceeds 2048 ----
    unsigned Tref = 0;
    if (M > 2048) {
        if (tid < 256) h256[tid] = 0;
        if (tid == 0) s_c0 = 0;
        __syncthreads();
        const unsigned binT = d_T[bl] >> 16;
        const int rounds = (M + 1023) >> 10;
        for (int r = 0; r < rounds; ++r) {
            int i = tid + (r << 10);
            bool in = i < M;
            unsigned u = in ? (unsigned)(gc[i] >> 32) : 0u;
            bool above = in && ((u >> 16) > binT);
            unsigned mb = __ballot_sync(0xffffffffu, above);
            if (lane == 0 && mb) atomicAdd(&s_c0, __popc(mb));
            if (in && ((u >> 16) == binT)) atomicAdd(&h256[(u >> 8) & 0xFFu], 1);
        }
        __syncthreads();
        if (tid == 0) {
            int cum = s_c0, b2 = 0;
            for (int s = 255; s >= 0; --s) {
                cum += h256[s];
                if (cum >= K) { b2 = s; break; }
            }
            s_b2 = b2;
        }
        __syncthreads();
        Tref = (binT << 16) | ((unsigned)s_b2 << 8);
    }

    // ---- Filtered load into smem (warp-aggregated) ----
    if (tid == 0) s_cnt2 = 0;
    __syncthreads();
    {
        const int rounds = (M + 1023) >> 10;
        for (int r = 0; r < rounds; ++r) {
            int i = tid + (r << 10);
            bool in = i < M;
            unsigned long long key = in ? gc[i] : 0ull;
            bool take = in && ((unsigned)(key >> 32) >= Tref);
            int p = warpAppend(&s_cnt2, take);
            if (take && p < SORT_CAP) cand[p] = key;
        }
    }
    __syncthreads();
    const int Muse = min(s_cnt2, SORT_CAP);
    int S = 1024;
    while (S < Muse) S <<= 1;
    for (int i = tid; i < S; i += 1024)
        if (i >= Muse) cand[i] = 0ull;
    __syncthreads();

    // ---- Bitonic sort descending (S keys) ----
    for (int k = 2; k <= S; k <<= 1) {
        for (int j = k >> 1; j > 0; j >>= 1) {
            for (int idx = tid; idx < S; idx += 1024) {
                int ixj = idx ^ j;
                if (ixj > idx) {
                    unsigned long long a = cand[idx], c2 = cand[ixj];
                    bool desc = (idx & k) == 0;
                    if (desc ? (a < c2) : (a > c2)) { cand[idx] = c2; cand[ixj] = a; }
                }
            }
            __syncthreads();
        }
    }

    // ---- Write top-K + inline decode/clip (bit-matching FP) ----
    const float* rg = pick(r0, r1, r2, r3, r4, l);
    const int A = c_A[l];
    const int g = c_grid[l];
    const float strf = (float)c_stride[l];
    const float* in2 = info + b * 3;
    const float H = __fsub_rn(in2[0], 1.0f);
    const float W = __fsub_rn(in2[1], 1.0f);

    for (int j = tid; j < K; j += 1024) {
        unsigned long long key = cand[j];
        const int idx = (int)(~(unsigned)key);
        d_topIdx [bl * PRE_NMS + j] = idx;
        d_topScore[bl * PRE_NMS + j] = iordf((unsigned)(key >> 32));

        const int cell = idx / 3, a = idx - cell * 3;
        const int iy = cell / g, ix = cell - iy * g;

        float cx = __fmul_rn((float)ix + 0.5f, strf);
        float cy = __fmul_rn((float)iy + 0.5f, strf);

        float aw = s_aw[a];
        float ah = s_ah[a];

        float x1a = __fsub_rn(cx, __fmul_rn(0.5f, aw));
        float y1a = __fsub_rn(cy, __fmul_rn(0.5f, ah));
        float x2a = __fadd_rn(cx, __fmul_rn(0.5f, aw));
        float y2a = __fadd_rn(cy, __fmul_rn(0.5f, ah));

        float wa = __fsub_rn(x2a, x1a);
        float ha = __fsub_rn(y2a, y1a);
        float cxa = __fadd_rn(x1a, __fmul_rn(0.5f, wa));
        float cya = __fadd_rn(y1a, __fmul_rn(0.5f, ha));

        const float* rp = rg + ((size_t)b * A + idx) * 4;
        float dx = rp[0], dy = rp[1], dw = rp[2], dh = rp[3];

        float ncx = __fadd_rn(__fmul_rn(dx, wa), cxa);
        float ncy = __fadd_rn(__fmul_rn(dy, ha), cya);
        float nw  = __fmul_rn(expf(dw), wa);
        float nh  = __fmul_rn(expf(dh), ha);

        float x1 = __fsub_rn(ncx, __fmul_rn(0.5f, nw));
        float y1 = __fsub_rn(ncy, __fmul_rn(0.5f, nh));
        float x2 = __fadd_rn(ncx, __fmul_rn(0.5f, nw));
        float y2 = __fadd_rn(ncy, __fmul_rn(0.5f, nh));

        x1 = fminf(fmaxf(x1, 0.0f), W);
        x2 = fminf(fmaxf(x2, 0.0f), W);
        y1 = fminf(fmaxf(y1, 0.0f), H);
        y2 = fminf(fmaxf(y2, 0.0f), H);

        d_topBoxes[bl * PRE_NMS + j] = make_float4(x1, y1, x2, y2);
    }
}

// ---------------------------------------------------------------------------
// Kernel 4: IoU mask (16 tiles/block) + (last block per bl) pipelined reduce.
// grid (MBLOCKS, NBL) x 1024. Division-free bracket accept, transposed
// coalesced mask layout. Winner = arrival with old % MBLOCKS == MBLOCKS-1.
// ---------------------------------------------------------------------------
__global__ __launch_bounds__(1024)
void mask_reduce_kernel() {
    const int bl = blockIdx.y;
    const int l = bl % NLEV;
    const int N = c_K[l];
    const int KP = c_KP[l];
    const int tid = threadIdx.x;
    const int warp = tid >> 5;
    const int lane = tid & 31;

    __shared__ __align__(16) unsigned char su[32768];    // stage union
    __shared__ unsigned long long s_rem[32], s_keep[32];
    __shared__ int s_win;

    // ================== Phase 1: 16 mask tiles ==================
    {
        float4* cbx  = (float4*)su;                       // 16*64*16 = 16 KB
        float*  care = (float*)(su + 16384);              // 16*64*4  =  4 KB
        const int grp = tid >> 6;
        const int gl  = tid & 63;
        const int job = blockIdx.x * 16 + grp;            // 0..527

        int t = job, y = 0;
        while (t >= NTILE - y) { t -= NTILE - y; ++y; }
        const int x = y + t;
        const int rowStart = y << 6;
        const int colStart = x << 6;
        const bool active = (rowStart < N) && (colStart < N);

        if (active) {
            int jj = colStart + gl;
            float4 cj = (jj < N) ? d_topBoxes[bl * PRE_NMS + jj]
                                 : make_float4(0.f, 0.f, 0.f, 0.f);
            cbx[(grp << 6) + gl] = cj;
            care[(grp << 6) + gl] = __fmul_rn(fmaxf(__fsub_rn(cj.z, cj.x), 0.0f),
                                              fmaxf(__fsub_rn(cj.w, cj.y), 0.0f));
        }
        __syncthreads();
        if (active) {
            const int i = rowStart + gl;
            if (i < N) {
                float4 bi = d_topBoxes[bl * PRE_NMS + i];
                float ai = __fmul_rn(fmaxf(__fsub_rn(bi.z, bi.x), 0.0f),
                                     fmaxf(__fsub_rn(bi.w, bi.y), 0.0f));
                unsigned long long bits = 0ull;
                #pragma unroll 8
                for (int jl = 0; jl < 64; ++jl) {
                    int jg = colStart + jl;
                    if (jg <= i || jg >= N) continue;
                    float4 bj = cbx[(grp << 6) + jl];
                    float xx1 = fmaxf(bi.x, bj.x), yy1 = fmaxf(bi.y, bj.y);
                    float xx2 = fminf(bi.z, bj.z), yy2 = fminf(bi.w, bj.w);
                    float w = fmaxf(__fsub_rn(xx2, xx1), 0.0f);
                    float h = fmaxf(__fsub_rn(yy2, yy1), 0.0f);
                    float inter = __fmul_rn(w, h);
                    float aj = care[(grp << 6) + jl];
                    float uni = fmaxf(__fsub_rn(__fadd_rn(ai, aj), inter), 1e-9f);
                    float tcut = __fmul_rn(0.7f, uni);
                    if (inter > __fmul_rn(tcut, 1.00001f)) {
                        bits |= (1ull << jl);
                    } else if (inter >= __fmul_rn(tcut, 0.99999f)) {
                        if (__fdiv_rn(inter, uni) > 0.7f) bits |= (1ull << jl);
                    }
                }
                d_maskT[((size_t)bl * 32 + x) * PRE_NMS + i] = bits;
            }
        }
    }

    // ================== arrive; last block continues into reduce ==========
    __threadfence();
    __syncthreads();
    if (tid == 0) {
        unsigned old = atomicAdd(&d_done2[bl], 1u);
        s_win = ((old % MBLOCKS) == (MBLOCKS - 1)) ? 1 : 0;
    }
    __syncthreads();
    if (!s_win) return;
    __threadfence();                     // acquire: all mask writes visible

    // ================== Phase 2: pipelined warp-specialized reduce ========
    unsigned long long* s_diag = (unsigned long long*)su;           // 16 KB
    int* sA = (int*)(su + 16384);                                   //  8 KB
    int* sB = (int*)(su + 16384 + 8192);                            //  8 KB

    const unsigned long long* mT = d_maskT + (size_t)bl * 32 * PRE_NMS;
    const int NC = (N + 63) >> 6;

    __syncthreads();                     // su reuse: phase-1 reads done
    for (int i = tid; i < (NC << 6); i += 1024)
        s_diag[i] = (i < N) ? mT[(size_t)(i >> 6) * PRE_NMS + i] : 0ull;
    if (tid < 32) s_rem[tid] = 0ull;
    __syncthreads();

    unsigned long long kreg = 0ull;

    for (int c = 0; c < NC; ++c) {
        const int cc = c + warp;
        const bool doCol = (c > 0) && (cc < NC);
        unsigned long long m0 = 0ull, m1 = 0ull;
        if (doCol) {
            const int rbase = (c - 1) << 6;
            const unsigned long long* colp = mT + (size_t)cc * PRE_NMS + rbase;
            m0 = colp[lane];
            m1 = colp[32 + lane];
        }
        __syncthreads();

        unsigned long long myContrib = 0ull;
        if (doCol) {
            unsigned long long kprev = (warp == 0) ? kreg : s_keep[c - 1];
            unsigned kl = (unsigned)kprev, kh = (unsigned)(kprev >> 32);
            unsigned long long v = 0ull;
            if ((kl >> lane) & 1u) v |= m0;
            if ((kh >> lane) & 1u) v |= m1;
            unsigned vlo = __reduce_or_sync(0xffffffffu, (unsigned)v);
            unsigned vhi = __reduce_or_sync(0xffffffffu, (unsigned)(v >> 32));
            unsigned long long vv = ((unsigned long long)vhi << 32) | vlo;
            if (warp == 0) myContrib = vv;
            else if (lane == 0) s_rem[cc] |= vv;
        }

        if (warp == 0) {
            unsigned long long rem = s_rem[c] | myContrib;
            unsigned rlo = (unsigned)rem, rhi = (unsigned)(rem >> 32);
            unsigned nklo = 0, nkhi = 0;
            const unsigned long long* dg = s_diag + (c << 6);
            #pragma unroll
            for (int k = 0; k < 32; ++k) {
                unsigned s = (unsigned)((int)(rlo << (31 - k)) >> 31);
                unsigned long long m = dg[k];
                rlo |= (unsigned)m & ~s;
                rhi |= (unsigned)(m >> 32) & ~s;
                nklo |= ~s & (1u << k);
            }
            #pragma unroll
            for (int k = 0; k < 32; ++k) {
                unsigned s = (unsigned)((int)(rhi << (31 - k)) >> 31);
                unsigned long long m = dg[32 + k];
                rhi |= (unsigned)(m >> 32) & ~s;
                nkhi |= ~s & (1u << k);
            }
            unsigned long long keepw = ((unsigned long long)nkhi << 32) | nklo;
            const int nr = N - (c << 6);
            if (nr < 64) keepw &= (1ull << nr) - 1ull;
            if (lane == 0) s_keep[c] = keepw;
            kreg = keepw;
        }
    }
    __syncthreads();

    for (int j = tid; j < 2048; j += 1024) {
        int kept = 0;
        if (j < N) kept = (int)((s_keep[j >> 6] >> (j & 63)) & 1ull);
        sA[j] = kept;
    }
    __syncthreads();

    int* src = sA; int* dst = sB;
    for (int off = 1; off < 2048; off <<= 1) {
        for (int j = tid; j < 2048; j += 1024)
            dst[j] = src[j] + ((j >= off) ? src[j - off] : 0);
        __syncthreads();
        int* t = src; src = dst; dst = t;
    }
    const int total = src[2047];

    for (int j = tid; j < N; j += 1024) {
        int kept = (int)((s_keep[j >> 6] >> (j & 63)) & 1ull);
        int incl = src[j];
        if (kept) {
            int rank = incl - 1;
            if (rank < KP) {
                d_lvlScore[bl * POST_NMS + rank] = d_topScore[bl * PRE_NMS + j];
                d_lvlPos  [bl * POST_NMS + rank] = j;
            }
        } else {
            int rank = total + (j - incl);
            if (rank < KP) {
                d_lvlScore[bl * POST_NMS + rank] = -1.0f;
                d_lvlPos  [bl * POST_NMS + rank] = j;
            }
        }
    }
}

// ---------------------------------------------------------------------------
// Kernel 5: final cross-level top-1000 via rank-by-binary-search.
// ---------------------------------------------------------------------------
__global__ __launch_bounds__(1024)
void final_kernel(float* __restrict__ out) {
    const int b = blockIdx.x;
    const int tid = threadIdx.x;
    __shared__ unsigned long long key[TOTCAT];

    for (int c = tid; c < TOTCAT; c += 1024) {
        int l = (c < 4000) ? (c / 1000) : 4;
        int pos = c - l * 1000;
        float s = d_lvlScore[(b * NLEV + l) * POST_NMS + pos];
        key[c] = ((unsigned long long)ordf(s) << 32) | (unsigned)(~c);
    }
    __syncthreads();

    const int segN[NLEV] = {1000, 1000, 1000, 1000, 768};
    for (int c = tid; c < TOTCAT; c += 1024) {
        unsigned long long ke = key[c];
        int rank = 0;
        #pragma unroll
        for (int l2 = 0; l2 < NLEV; ++l2) {
            const int base2 = l2 * 1000;
            int lo = 0, hi = segN[l2];
            while (lo < hi) {
                int mid = (lo + hi) >> 1;
                if (key[base2 + mid] > ke) lo = mid + 1; else hi = mid;
            }
            rank += lo;
        }
        if (rank < POST_NMS) {
            unsigned hi32 = (unsigned)(ke >> 32);
            int l = (c < 4000) ? (c / 1000) : 4;
            int pos = c - l * 1000;
            float* o = out + ((size_t)b * POST_NMS + rank) * 5;
            o[0] = (float)b;
            if (hi32 & 0x80000000u) {   // score >= 0
                int blx = b * NLEV + l;
                int j = d_lvlPos[blx * POST_NMS + pos];
                float4 bx = d_topBoxes[blx * PRE_NMS + j];
                o[1] = bx.x; o[2] = bx.y; o[3] = bx.z; o[4] = bx.w;
            } else {
                o[1] = 0.0f; o[2] = 0.0f; o[3] = 0.0f; o[4] = 0.0f;
            }
        }
    }
}

// ---------------------------------------------------------------------------
// Launcher — inputs identified BY ELEMENT COUNT (all 11 sizes distinct).
// 5 graph nodes, no memsets (d_hist zero-invariant maintained by winners).
// ---------------------------------------------------------------------------
extern "C" void kernel_launch(void* const* d_in, const int* in_sizes, int n_in,
                              void* d_out, int out_size) {
    const float* probs[NLEV] = {0, 0, 0, 0, 0};
    const float* regs [NLEV] = {0, 0, 0, 0, 0};
    const float* info = 0;

    for (int i = 0; i < n_in; ++i) {
        const float* p = (const float*)d_in[i];
        switch (in_sizes[i]) {
            case 4 * 196608 * 2: probs[0] = p; break;
            case 4 * 196608 * 4: regs [0] = p; break;
            case 4 * 49152 * 2:  probs[1] = p; break;
            case 4 * 49152 * 4:  regs [1] = p; break;
            case 4 * 12288 * 2:  probs[2] = p; break;
            case 4 * 12288 * 4:  regs [2] = p; break;
            case 4 * 3072 * 2:   probs[3] = p; break;
            case 4 * 3072 * 4:   regs [3] = p; break;
            case 4 * 768 * 2:    probs[4] = p; break;
            case 4 * 768 * 4:    regs [4] = p; break;
            case 12:             info = p; break;
            default: break;
        }
    }
    float* out = (float*)d_out;

    hist_select_kernel<<<dim3(HBLOCKS, NBL), 1024>>>(probs[0], probs[1], probs[2], probs[3], probs[4]);
    compact_kernel<<<dim3(64, NBL), 256>>>(probs[0], probs[1], probs[2], probs[3], probs[4]);
    sort_decode_kernel<<<NBL, 1024>>>(regs[0], regs[1], regs[2], regs[3], regs[4], info);
    mask_reduce_kernel<<<dim3(MBLOCKS, NBL), 1024>>>();
    final_kernel<<<BATCH, 1024>>>(out);
}

// round 13
// speedup vs baseline: 1.6967x; 1.6967x over previous
#include <cuda_runtime.h>
#include <cstdint>

// ---------------------------------------------------------------------------
// Problem constants
// ---------------------------------------------------------------------------
#define NLEV 5
#define BATCH 4
#define PRE_NMS 2000
#define POST_NMS 1000
#define NBL (BATCH * NLEV)          // 20 (batch, level) pairs
#define SORT_CAP 4096               // max bitonic capacity
#define TOTCAT 4768                 // 4*1000 + 768 concatenated entries
#define HBINS 65536
#define NTILE 32                    // 2000/64 -> 32 tiles
#define NTRI  528                   // 32*33/2 upper-triangle tile pairs
#define MTPB  2                     // mask tiles per block
#define MGRID (NTRI / MTPB)         // 264 mask blocks per bl

__constant__ int c_A[NLEV]      = {196608, 49152, 12288, 3072, 768};
__constant__ int c_K[NLEV]      = {2000, 2000, 2000, 2000, 768};
__constant__ int c_KP[NLEV]     = {1000, 1000, 1000, 1000, 768};
__constant__ int c_stride[NLEV] = {4, 8, 16, 32, 64};
__constant__ int c_grid[NLEV]   = {256, 128, 64, 32, 16};
__constant__ int c_base[NLEV]   = {32, 64, 128, 256, 512};

// ---------------------------------------------------------------------------
// Device scratch (static allocation only)
// ---------------------------------------------------------------------------
__device__ int                 d_hist   [NBL * HBINS];      // 5.2 MB
__device__ unsigned            d_T      [NBL];
__device__ int                 d_cnt    [NBL];
__device__ unsigned long long  d_cand   [NBL * SORT_CAP];
__device__ int                 d_topIdx [NBL * PRE_NMS];
__device__ float               d_topScore[NBL * PRE_NMS];
__device__ float4              d_topBoxes[NBL * PRE_NMS];
__device__ unsigned long long  d_maskT  [NBL * 32 * PRE_NMS];   // [(bl*32+col)*2000+row]
__device__ float               d_lvlScore[NBL * POST_NMS];
__device__ int                 d_lvlPos  [NBL * POST_NMS];

// ---------------------------------------------------------------------------
// Helpers
// ---------------------------------------------------------------------------
__device__ __forceinline__ unsigned ordf(float f) {
    unsigned u = __float_as_uint(f);
    return (u & 0x80000000u) ? ~u : (u | 0x80000000u);
}
__device__ __forceinline__ float iordf(unsigned u) {
    unsigned v = (u & 0x80000000u) ? (u & 0x7FFFFFFFu) : ~u;
    return __uint_as_float(v);
}
__device__ __forceinline__ const float* pick(const float* a0, const float* a1,
                                             const float* a2, const float* a3,
                                             const float* a4, int l) {
    switch (l) { case 0: return a0; case 1: return a1; case 2: return a2;
                 case 3: return a3; default: return a4; }
}
// Warp-aggregated append; all 32 lanes must execute (use padded loops).
__device__ __forceinline__ int warpAppend(int* ctr, bool pred) {
    unsigned m = __ballot_sync(0xffffffffu, pred);
    int lane = threadIdx.x & 31;
    int base = 0;
    if (m != 0) {
        int leader = __ffs(m) - 1;
        if (lane == leader) base = atomicAdd(ctr, __popc(m));
        base = __shfl_sync(0xffffffffu, base, leader);
    }
    return pred ? base + __popc(m & ((1u << lane) - 1u)) : -1;
}

// ---------------------------------------------------------------------------
// Kernel 1a: parallel 16-bit histogram over ordered score keys.
// ---------------------------------------------------------------------------
__global__ __launch_bounds__(256)
void hist_kernel(const float* __restrict__ p0, const float* __restrict__ p1,
                 const float* __restrict__ p2, const float* __restrict__ p3,
                 const float* __restrict__ p4) {
    const int bl = blockIdx.y;
    const int b = bl / NLEV, l = bl % NLEV;
    const int A = c_A[l];
    const float2* base2 = (const float2*)(pick(p0, p1, p2, p3, p4, l) + (size_t)b * A * 2);
    int* hist = d_hist + (size_t)bl * HBINS;

    const int chunk = (A + 63) >> 6;
    const int start = blockIdx.x * chunk;
    const int end = min(start + chunk, A);
    for (int i = start + threadIdx.x; i < end; i += 256) {
        unsigned u = ordf(base2[i].x);
        atomicAdd(&hist[u >> 16], 1);
    }
}

// ---------------------------------------------------------------------------
// Kernel 1b: per-bl coarse threshold select; also zeroes d_cnt[bl].
// ---------------------------------------------------------------------------
__global__ __launch_bounds__(1024)
void select_kernel() {
    const int bl = blockIdx.x;
    const int l = bl % NLEV;
    const int K = c_K[l];
    const int tid = threadIdx.x;
    const int* hist = d_hist + (size_t)bl * HBINS;

    __shared__ int sA[1024], sB[1024];

    if (tid == 0) d_cnt[bl] = 0;

    const int hi = HBINS - 1 - (tid << 6);
    int sum = 0;
    #pragma unroll 8
    for (int k = 0; k < 64; ++k) sum += hist[hi - k];
    sA[tid] = sum;
    __syncthreads();

    int* src = sA; int* dst = sB;
    for (int off = 1; off < 1024; off <<= 1) {
        dst[tid] = src[tid] + ((tid >= off) ? src[tid - off] : 0);
        __syncthreads();
        int* t2 = src; src = dst; dst = t2;
    }

    const int prev = (tid == 0) ? 0 : src[tid - 1];
    if (src[tid] >= K && prev < K) {
        int cum = prev;
        unsigned Tb = 0;
        for (int k = 0; k < 64; ++k) {
            cum += hist[hi - k];
            if (cum >= K) { Tb = (unsigned)(hi - k); break; }
        }
        d_T[bl] = Tb << 16;
    }
}

// ---------------------------------------------------------------------------
// Kernel 1c: parallel compaction of u >= T into per-bl candidate list.
// ---------------------------------------------------------------------------
__global__ __launch_bounds__(256)
void compact_kernel(const float* __restrict__ p0, const float* __restrict__ p1,
                    const float* __restrict__ p2, const float* __restrict__ p3,
                    const float* __restrict__ p4) {
    const int bl = blockIdx.y;
    const int b = bl / NLEV, l = bl % NLEV;
    const int A = c_A[l];
    const float2* base2 = (const float2*)(pick(p0, p1, p2, p3, p4, l) + (size_t)b * A * 2);
    const unsigned T = d_T[bl];
    unsigned long long* cand = d_cand + (size_t)bl * SORT_CAP;
    const int lane = threadIdx.x & 31;

    const int chunk = (A + 63) >> 6;
    const int start = blockIdx.x * chunk;
    const int end = min(start + chunk, A);
    const int n = end - start;
    const int rounds = (n + 255) >> 8;
    for (int r = 0; r < rounds; ++r) {
        int i = start + threadIdx.x + (r << 8);
        bool in = i < end;
        unsigned u = 0;
        if (in) u = ordf(base2[i].x);
        bool take = in && (u >= T);
        unsigned m = __ballot_sync(0xffffffffu, take);
        if (m) {
            int leader = __ffs(m) - 1;
            int basep = 0;
            if (lane == leader) basep = atomicAdd(&d_cnt[bl], __popc(m));
            basep = __shfl_sync(0xffffffffu, basep, leader);
            if (take) {
                int p = basep + __popc(m & ((1u << lane) - 1u));
                if (p < SORT_CAP)
                    cand[p] = ((unsigned long long)u << 32) | (unsigned)(~i);
            }
        }
    }
}

// ---------------------------------------------------------------------------
// Kernel 1d: per-bl threshold REFINEMENT (24-bit) + bitonic sort + decode.
// Anchor w/h precomputed once per block (same double math -> identical bits).
// ---------------------------------------------------------------------------
__global__ __launch_bounds__(1024)
void sort_decode_kernel(const float* __restrict__ r0, const float* __restrict__ r1,
                        const float* __restrict__ r2, const float* __restrict__ r3,
                        const float* __restrict__ r4, const float* __restrict__ info) {
    const int bl = blockIdx.x;
    const int b = bl / NLEV, l = bl % NLEV;
    const int K = c_K[l];
    const int tid = threadIdx.x;
    const int lane = tid & 31;

    __shared__ unsigned long long cand[SORT_CAP];   // 32 KB
    __shared__ int h256[256];
    __shared__ int s_c0, s_b2, s_cnt2;
    __shared__ float s_aw[3], s_ah[3];

    if (tid < 3) {
        double rr = (tid == 0) ? 0.5 : ((tid == 1) ? 1.0 : 2.0);
        double sb = (double)c_base[l] * 8.0;
        s_aw[tid] = (float)(sb * sqrt(1.0 / rr));
        s_ah[tid] = (float)(sb * sqrt(rr));
    }

    const unsigned long long* gc = d_cand + (size_t)bl * SORT_CAP;
    const int M = min(d_cnt[bl], SORT_CAP);

    // ---- Refine threshold to 24 bits when the coarse set exceeds 2048 ----
    unsigned Tref = 0;
    if (M > 2048) {
        if (tid < 256) h256[tid] = 0;
        if (tid == 0) s_c0 = 0;
        __syncthreads();
        const unsigned binT = d_T[bl] >> 16;
        const int rounds = (M + 1023) >> 10;
        for (int r = 0; r < rounds; ++r) {
            int i = tid + (r << 10);
            bool in = i < M;
            unsigned u = in ? (unsigned)(gc[i] >> 32) : 0u;
            bool above = in && ((u >> 16) > binT);
            unsigned mb = __ballot_sync(0xffffffffu, above);
            if (lane == 0 && mb) atomicAdd(&s_c0, __popc(mb));
            if (in && ((u >> 16) == binT)) atomicAdd(&h256[(u >> 8) & 0xFFu], 1);
        }
        __syncthreads();
        if (tid == 0) {
            int cum = s_c0, b2 = 0;
            for (int s = 255; s >= 0; --s) {
                cum += h256[s];
                if (cum >= K) { b2 = s; break; }
            }
            s_b2 = b2;
        }
        __syncthreads();
        Tref = (binT << 16) | ((unsigned)s_b2 << 8);
    }

    // ---- Filtered load into smem (warp-aggregated) ----
    if (tid == 0) s_cnt2 = 0;
    __syncthreads();
    {
        const int rounds = (M + 1023) >> 10;
        for (int r = 0; r < rounds; ++r) {
            int i = tid + (r << 10);
            bool in = i < M;
            unsigned long long key = in ? gc[i] : 0ull;
            bool take = in && ((unsigned)(key >> 32) >= Tref);
            int p = warpAppend(&s_cnt2, take);
            if (take && p < SORT_CAP) cand[p] = key;
        }
    }
    __syncthreads();
    const int Muse = min(s_cnt2, SORT_CAP);
    int S = 1024;
    while (S < Muse) S <<= 1;
    for (int i = tid; i < S; i += 1024)
        if (i >= Muse) cand[i] = 0ull;
    __syncthreads();

    // ---- Bitonic sort descending (S keys) ----
    for (int k = 2; k <= S; k <<= 1) {
        for (int j = k >> 1; j > 0; j >>= 1) {
            for (int idx = tid; idx < S; idx += 1024) {
                int ixj = idx ^ j;
                if (ixj > idx) {
                    unsigned long long a = cand[idx], c2 = cand[ixj];
                    bool desc = (idx & k) == 0;
                    if (desc ? (a < c2) : (a > c2)) { cand[idx] = c2; cand[ixj] = a; }
                }
            }
            __syncthreads();
        }
    }

    // ---- Write top-K + inline decode/clip (bit-matching FP) ----
    const float* rg = pick(r0, r1, r2, r3, r4, l);
    const int A = c_A[l];
    const int g = c_grid[l];
    const float strf = (float)c_stride[l];
    const float* in2 = info + b * 3;
    const float H = __fsub_rn(in2[0], 1.0f);
    const float W = __fsub_rn(in2[1], 1.0f);

    for (int j = tid; j < K; j += 1024) {
        unsigned long long key = cand[j];
        const int idx = (int)(~(unsigned)key);
        d_topIdx [bl * PRE_NMS + j] = idx;
        d_topScore[bl * PRE_NMS + j] = iordf((unsigned)(key >> 32));

        const int cell = idx / 3, a = idx - cell * 3;
        const int iy = cell / g, ix = cell - iy * g;

        float cx = __fmul_rn((float)ix + 0.5f, strf);
        float cy = __fmul_rn((float)iy + 0.5f, strf);

        float aw = s_aw[a];
        float ah = s_ah[a];

        float x1a = __fsub_rn(cx, __fmul_rn(0.5f, aw));
        float y1a = __fsub_rn(cy, __fmul_rn(0.5f, ah));
        float x2a = __fadd_rn(cx, __fmul_rn(0.5f, aw));
        float y2a = __fadd_rn(cy, __fmul_rn(0.5f, ah));

        float wa = __fsub_rn(x2a, x1a);
        float ha = __fsub_rn(y2a, y1a);
        float cxa = __fadd_rn(x1a, __fmul_rn(0.5f, wa));
        float cya = __fadd_rn(y1a, __fmul_rn(0.5f, ha));

        const float* rp = rg + ((size_t)b * A + idx) * 4;
        float dx = rp[0], dy = rp[1], dw = rp[2], dh = rp[3];

        float ncx = __fadd_rn(__fmul_rn(dx, wa), cxa);
        float ncy = __fadd_rn(__fmul_rn(dy, ha), cya);
        float nw  = __fmul_rn(expf(dw), wa);
        float nh  = __fmul_rn(expf(dh), ha);

        float x1 = __fsub_rn(ncx, __fmul_rn(0.5f, nw));
        float y1 = __fsub_rn(ncy, __fmul_rn(0.5f, nh));
        float x2 = __fadd_rn(ncx, __fmul_rn(0.5f, nw));
        float y2 = __fadd_rn(ncy, __fmul_rn(0.5f, nh));

        x1 = fminf(fmaxf(x1, 0.0f), W);
        x2 = fminf(fmaxf(x2, 0.0f), W);
        y1 = fminf(fmaxf(y1, 0.0f), H);
        y2 = fminf(fmaxf(y2, 0.0f), H);

        d_topBoxes[bl * PRE_NMS + j] = make_float4(x1, y1, x2, y2);
    }
}

// ---------------------------------------------------------------------------
// Kernel 2: NMS suppression-mask — upper-triangle tiles, division-free
// bracket accept, transposed coalesced writes. 2 tiles per 128-thread block
// (independent tile groups, disjoint smem) to halve block count.
// ---------------------------------------------------------------------------
__global__ __launch_bounds__(128)
void nms_mask_kernel() {
    const int bl = blockIdx.y;
    const int l = bl % NLEV;
    const int N = c_K[l];

    const int grp = threadIdx.x >> 6;      // 0..1
    const int tt  = threadIdx.x & 63;
    const int job = blockIdx.x * MTPB + grp;   // 0..527

    int t = job, y = 0;
    while (t >= NTILE - y) { t -= NTILE - y; ++y; }
    const int x = y + t;

    const int rowStart = y << 6;
    const int colStart = x << 6;
    const bool active = (rowStart < N) && (colStart < N);

    __shared__ float4 cbx[MTPB * 64];
    __shared__ float carea[MTPB * 64];

    if (active) {
        int jj = colStart + tt;
        float4 cj = (jj < N) ? d_topBoxes[bl * PRE_NMS + jj] : make_float4(0.f, 0.f, 0.f, 0.f);
        cbx[(grp << 6) + tt] = cj;
        carea[(grp << 6) + tt] = __fmul_rn(fmaxf(__fsub_rn(cj.z, cj.x), 0.0f),
                                           fmaxf(__fsub_rn(cj.w, cj.y), 0.0f));
    }
    __syncthreads();

    if (!active) return;
    const int i = rowStart + tt;
    if (i >= N) return;
    float4 bi = d_topBoxes[bl * PRE_NMS + i];
    float ai = __fmul_rn(fmaxf(__fsub_rn(bi.z, bi.x), 0.0f),
                         fmaxf(__fsub_rn(bi.w, bi.y), 0.0f));
    unsigned long long bits = 0ull;
    #pragma unroll 8
    for (int jl = 0; jl < 64; ++jl) {
        int jg = colStart + jl;
        if (jg <= i || jg >= N) continue;
        float4 bj = cbx[(grp << 6) + jl];
        float xx1 = fmaxf(bi.x, bj.x), yy1 = fmaxf(bi.y, bj.y);
        float xx2 = fminf(bi.z, bj.z), yy2 = fminf(bi.w, bj.w);
        float w = fmaxf(__fsub_rn(xx2, xx1), 0.0f);
        float h = fmaxf(__fsub_rn(yy2, yy1), 0.0f);
        float inter = __fmul_rn(w, h);
        float aj = carea[(grp << 6) + jl];
        float uni = fmaxf(__fsub_rn(__fadd_rn(ai, aj), inter), 1e-9f);
        float tcut = __fmul_rn(0.7f, uni);
        if (inter > __fmul_rn(tcut, 1.00001f)) {
            bits |= (1ull << jl);                       // definitely IoU > 0.7
        } else if (inter >= __fmul_rn(tcut, 0.99999f)) {
            if (__fdiv_rn(inter, uni) > 0.7f)           // ambiguous band: exact
                bits |= (1ull << jl);
        }
    }
    d_maskT[((size_t)bl * 32 + x) * PRE_NMS + i] = bits;   // coalesced across tt
}

// ---------------------------------------------------------------------------
// Kernel 3: pipelined warp-specialized NMS reduce (transposed coalesced loads).
// ---------------------------------------------------------------------------
__global__ __launch_bounds__(1024)
void nms_reduce_kernel() {
    const int bl = blockIdx.x;
    const int l = bl % NLEV;
    const int N = c_K[l];
    const int KP = c_KP[l];
    const int tid = threadIdx.x;
    const int warp = tid >> 5;
    const int lane = tid & 31;

    __shared__ unsigned long long s_diag[2048];
    __shared__ unsigned long long s_rem[32];
    __shared__ unsigned long long s_keep[32];
    __shared__ int sA[2048], sB[2048];

    const unsigned long long* mT = d_maskT + (size_t)bl * 32 * PRE_NMS;
    const int NC = (N + 63) >> 6;

    for (int i = tid; i < (NC << 6); i += 1024)
        s_diag[i] = (i < N) ? mT[(size_t)(i >> 6) * PRE_NMS + i] : 0ull;
    if (tid < 32) s_rem[tid] = 0ull;
    __syncthreads();

    unsigned long long kreg = 0ull;

    for (int c = 0; c < NC; ++c) {
        const int cc = c + warp;
        const bool doCol = (c > 0) && (cc < NC);
        unsigned long long m0 = 0ull, m1 = 0ull;
        if (doCol) {
            const int rbase = (c - 1) << 6;
            const unsigned long long* colp = mT + (size_t)cc * PRE_NMS + rbase;
            m0 = colp[lane];            // coalesced 256B
            m1 = colp[32 + lane];       // coalesced 256B
        }
        __syncthreads();

        unsigned long long myContrib = 0ull;
        if (doCol) {
            unsigned long long kprev = (warp == 0) ? kreg : s_keep[c - 1];
            unsigned kl = (unsigned)kprev, kh = (unsigned)(kprev >> 32);
            unsigned long long v = 0ull;
            if ((kl >> lane) & 1u) v |= m0;
            if ((kh >> lane) & 1u) v |= m1;
            unsigned vlo = __reduce_or_sync(0xffffffffu, (unsigned)v);
            unsigned vhi = __reduce_or_sync(0xffffffffu, (unsigned)(v >> 32));
            unsigned long long vv = ((unsigned long long)vhi << 32) | vlo;
            if (warp == 0) myContrib = vv;
            else if (lane == 0) s_rem[cc] |= vv;
        }

        if (warp == 0) {
            unsigned long long rem = s_rem[c] | myContrib;
            unsigned rlo = (unsigned)rem, rhi = (unsigned)(rem >> 32);
            unsigned nklo = 0, nkhi = 0;
            const unsigned long long* dg = s_diag + (c << 6);
            #pragma unroll
            for (int k = 0; k < 32; ++k) {
                unsigned s = (unsigned)((int)(rlo << (31 - k)) >> 31);
                unsigned long long m = dg[k];
                rlo |= (unsigned)m & ~s;
                rhi |= (unsigned)(m >> 32) & ~s;
                nklo |= ~s & (1u << k);
            }
            #pragma unroll
            for (int k = 0; k < 32; ++k) {
                unsigned s = (unsigned)((int)(rhi << (31 - k)) >> 31);
                unsigned long long m = dg[32 + k];
                rhi |= (unsigned)(m >> 32) & ~s;
                nkhi |= ~s & (1u << k);
            }
            unsigned long long keepw = ((unsigned long long)nkhi << 32) | nklo;
            const int nr = N - (c << 6);
            if (nr < 64) keepw &= (1ull << nr) - 1ull;
            if (lane == 0) s_keep[c] = keepw;
            kreg = keepw;
        }
    }
    __syncthreads();

    for (int j = tid; j < 2048; j += 1024) {
        int kept = 0;
        if (j < N) kept = (int)((s_keep[j >> 6] >> (j & 63)) & 1ull);
        sA[j] = kept;
    }
    __syncthreads();

    int* src = sA; int* dst = sB;
    for (int off = 1; off < 2048; off <<= 1) {
        for (int j = tid; j < 2048; j += 1024)
            dst[j] = src[j] + ((j >= off) ? src[j - off] : 0);
        __syncthreads();
        int* t = src; src = dst; dst = t;
    }
    const int total = src[2047];

    for (int j = tid; j < N; j += 1024) {
        int kept = (int)((s_keep[j >> 6] >> (j & 63)) & 1ull);
        int incl = src[j];
        if (kept) {
            int rank = incl - 1;
            if (rank < KP) {
                d_lvlScore[bl * POST_NMS + rank] = d_topScore[bl * PRE_NMS + j];
                d_lvlPos  [bl * POST_NMS + rank] = j;
            }
        } else {
            int rank = total + (j - incl);
            if (rank < KP) {
                d_lvlScore[bl * POST_NMS + rank] = -1.0f;
                d_lvlPos  [bl * POST_NMS + rank] = j;
            }
        }
    }
}

// ---------------------------------------------------------------------------
// Kernel 4: final cross-level top-1000 via rank-by-binary-search.
// ---------------------------------------------------------------------------
__global__ __launch_bounds__(1024)
void final_kernel(float* __restrict__ out) {
    const int b = blockIdx.x;
    const int tid = threadIdx.x;
    __shared__ unsigned long long key[TOTCAT];

    for (int c = tid; c < TOTCAT; c += 1024) {
        int l = (c < 4000) ? (c / 1000) : 4;
        int pos = c - l * 1000;
        float s = d_lvlScore[(b * NLEV + l) * POST_NMS + pos];
        key[c] = ((unsigned long long)ordf(s) << 32) | (unsigned)(~c);
    }
    __syncthreads();

    const int segN[NLEV] = {1000, 1000, 1000, 1000, 768};
    for (int c = tid; c < TOTCAT; c += 1024) {
        unsigned long long ke = key[c];
        int rank = 0;
        #pragma unroll
        for (int l2 = 0; l2 < NLEV; ++l2) {
            const int base2 = l2 * 1000;
            int lo = 0, hi = segN[l2];
            while (lo < hi) {
                int mid = (lo + hi) >> 1;
                if (key[base2 + mid] > ke) lo = mid + 1; else hi = mid;
            }
            rank += lo;
        }
        if (rank < POST_NMS) {
            unsigned hi32 = (unsigned)(ke >> 32);
            int l = (c < 4000) ? (c / 1000) : 4;
            int pos = c - l * 1000;
            float* o = out + ((size_t)b * POST_NMS + rank) * 5;
            o[0] = (float)b;
            if (hi32 & 0x80000000u) {   // score >= 0
                int blx = b * NLEV + l;
                int j = d_lvlPos[blx * POST_NMS + pos];
                float4 bx = d_topBoxes[blx * PRE_NMS + j];
                o[1] = bx.x; o[2] = bx.y; o[3] = bx.z; o[4] = bx.w;
            } else {
                o[1] = 0.0f; o[2] = 0.0f; o[3] = 0.0f; o[4] = 0.0f;
            }
        }
    }
}

// ---------------------------------------------------------------------------
// Launcher — inputs identified BY ELEMENT COUNT (all 11 sizes distinct).
// ---------------------------------------------------------------------------
extern "C" void kernel_launch(void* const* d_in, const int* in_sizes, int n_in,
                              void* d_out, int out_size) {
    const float* probs[NLEV] = {0, 0, 0, 0, 0};
    const float* regs [NLEV] = {0, 0, 0, 0, 0};
    const float* info = 0;

    for (int i = 0; i < n_in; ++i) {
        const float* p = (const float*)d_in[i];
        switch (in_sizes[i]) {
            case 4 * 196608 * 2: probs[0] = p; break;
            case 4 * 196608 * 4: regs [0] = p; break;
            case 4 * 49152 * 2:  probs[1] = p; break;
            case 4 * 49152 * 4:  regs [1] = p; break;
            case 4 * 12288 * 2:  probs[2] = p; break;
            case 4 * 12288 * 4:  regs [2] = p; break;
            case 4 * 3072 * 2:   probs[3] = p; break;
            case 4 * 3072 * 4:   regs [3] = p; break;
            case 4 * 768 * 2:    probs[4] = p; break;
            case 4 * 768 * 4:    regs [4] = p; break;
            case 12:             info = p; break;
            default: break;
        }
    }
    float* out = (float*)d_out;

    void* histPtr = 0;
    cudaGetSymbolAddress(&histPtr, d_hist);
    cudaMemsetAsync(histPtr, 0, (size_t)NBL * HBINS * sizeof(int));

    hist_kernel<<<dim3(64, NBL), 256>>>(probs[0], probs[1], probs[2], probs[3], probs[4]);
    select_kernel<<<NBL, 1024>>>();
    compact_kernel<<<dim3(64, NBL), 256>>>(probs[0], probs[1], probs[2], probs[3], probs[4]);
    sort_decode_kernel<<<NBL, 1024>>>(regs[0], regs[1], regs[2], regs[3], regs[4], info);
    nms_mask_kernel<<<dim3(MGRID, NBL), 128>>>();
    nms_reduce_kernel<<<NBL, 1024>>>();
    final_kernel<<<BATCH, 1024>>>(out);
}

// round 14
// speedup vs baseline: 1.7037x; 1.0041x over previous
#include <cuda_runtime.h>
#include <cstdint>

// ---------------------------------------------------------------------------
// Problem constants
// ---------------------------------------------------------------------------
#define NLEV 5
#define BATCH 4
#define PRE_NMS 2000
#define POST_NMS 1000
#define NBL (BATCH * NLEV)          // 20 (batch, level) pairs
#define SORT_CAP 4096               // max bitonic capacity
#define TOTCAT 4768                 // 4*1000 + 768 concatenated entries
#define HBINS 65536
#define NTILE 32                    // 2000/64 -> 32 tiles
#define NTRI  528                   // 32*33/2 upper-triangle tile pairs
#define MTPB  2                     // mask tiles per block
#define MGRID (NTRI / MTPB)         // 264 mask blocks per bl

__constant__ int c_A[NLEV]      = {196608, 49152, 12288, 3072, 768};
__constant__ int c_K[NLEV]      = {2000, 2000, 2000, 2000, 768};
__constant__ int c_KP[NLEV]     = {1000, 1000, 1000, 1000, 768};
__constant__ int c_stride[NLEV] = {4, 8, 16, 32, 64};
__constant__ int c_grid[NLEV]   = {256, 128, 64, 32, 16};
__constant__ int c_base[NLEV]   = {32, 64, 128, 256, 512};

// ---------------------------------------------------------------------------
// Device scratch (static allocation only)
// ---------------------------------------------------------------------------
__device__ int                 d_hist   [NBL * HBINS];      // 5.2 MB
__device__ unsigned            d_T      [NBL];
__device__ int                 d_cnt    [NBL];
__device__ unsigned long long  d_cand   [NBL * SORT_CAP];
__device__ int                 d_topIdx [NBL * PRE_NMS];
__device__ float               d_topScore[NBL * PRE_NMS];
__device__ float4              d_topBoxes[NBL * PRE_NMS];
__device__ unsigned long long  d_maskT  [NBL * 32 * PRE_NMS];   // [(bl*32+col)*2000+row]
__device__ float               d_lvlScore[NBL * POST_NMS];
__device__ int                 d_lvlPos  [NBL * POST_NMS];

// ---------------------------------------------------------------------------
// Helpers
// ---------------------------------------------------------------------------
__device__ __forceinline__ void grid_dep_wait() {
    // Blocks until the programmatic-dependency primary grid's memory is
    // visible. No-op when launched without the PDL attribute.
    asm volatile("griddepcontrol.wait;" ::: "memory");
}
__device__ __forceinline__ unsigned ordf(float f) {
    unsigned u = __float_as_uint(f);
    return (u & 0x80000000u) ? ~u : (u | 0x80000000u);
}
__device__ __forceinline__ float iordf(unsigned u) {
    unsigned v = (u & 0x80000000u) ? (u & 0x7FFFFFFFu) : ~u;
    return __uint_as_float(v);
}
__device__ __forceinline__ const float* pick(const float* a0, const float* a1,
                                             const float* a2, const float* a3,
                                             const float* a4, int l) {
    switch (l) { case 0: return a0; case 1: return a1; case 2: return a2;
                 case 3: return a3; default: return a4; }
}
// Warp-aggregated append; all 32 lanes must execute (use padded loops).
__device__ __forceinline__ int warpAppend(int* ctr, bool pred) {
    unsigned m = __ballot_sync(0xffffffffu, pred);
    int lane = threadIdx.x & 31;
    int base = 0;
    if (m != 0) {
        int leader = __ffs(m) - 1;
        if (lane == leader) base = atomicAdd(ctr, __popc(m));
        base = __shfl_sync(0xffffffffu, base, leader);
    }
    return pred ? base + __popc(m & ((1u << lane) - 1u)) : -1;
}

// ---------------------------------------------------------------------------
// Kernel 1a: parallel 16-bit histogram over ordered score keys.
// (normal launch — predecessor is a memset node)
// ---------------------------------------------------------------------------
__global__ __launch_bounds__(256)
void hist_kernel(const float* __restrict__ p0, const float* __restrict__ p1,
                 const float* __restrict__ p2, const float* __restrict__ p3,
                 const float* __restrict__ p4) {
    const int bl = blockIdx.y;
    const int b = bl / NLEV, l = bl % NLEV;
    const int A = c_A[l];
    const float2* base2 = (const float2*)(pick(p0, p1, p2, p3, p4, l) + (size_t)b * A * 2);
    int* hist = d_hist + (size_t)bl * HBINS;

    const int chunk = (A + 63) >> 6;
    const int start = blockIdx.x * chunk;
    const int end = min(start + chunk, A);
    for (int i = start + threadIdx.x; i < end; i += 256) {
        unsigned u = ordf(base2[i].x);
        atomicAdd(&hist[u >> 16], 1);
    }
}

// ---------------------------------------------------------------------------
// Kernel 1b: per-bl coarse threshold select; also zeroes d_cnt[bl]. (PDL)
// ---------------------------------------------------------------------------
__global__ __launch_bounds__(1024)
void select_kernel() {
    grid_dep_wait();
    const int bl = blockIdx.x;
    const int l = bl % NLEV;
    const int K = c_K[l];
    const int tid = threadIdx.x;
    const int* hist = d_hist + (size_t)bl * HBINS;

    __shared__ int sA[1024], sB[1024];

    if (tid == 0) d_cnt[bl] = 0;

    const int hi = HBINS - 1 - (tid << 6);
    int sum = 0;
    #pragma unroll 8
    for (int k = 0; k < 64; ++k) sum += hist[hi - k];
    sA[tid] = sum;
    __syncthreads();

    int* src = sA; int* dst = sB;
    for (int off = 1; off < 1024; off <<= 1) {
        dst[tid] = src[tid] + ((tid >= off) ? src[tid - off] : 0);
        __syncthreads();
        int* t2 = src; src = dst; dst = t2;
    }

    const int prev = (tid == 0) ? 0 : src[tid - 1];
    if (src[tid] >= K && prev < K) {
        int cum = prev;
        unsigned Tb = 0;
        for (int k = 0; k < 64; ++k) {
            cum += hist[hi - k];
            if (cum >= K) { Tb = (unsigned)(hi - k); break; }
        }
        d_T[bl] = Tb << 16;
    }
}

// ---------------------------------------------------------------------------
// Kernel 1c: parallel compaction of u >= T into per-bl candidate list. (PDL)
// ---------------------------------------------------------------------------
__global__ __launch_bounds__(256)
void compact_kernel(const float* __restrict__ p0, const float* __restrict__ p1,
                    const float* __restrict__ p2, const float* __restrict__ p3,
                    const float* __restrict__ p4) {
    grid_dep_wait();
    const int bl = blockIdx.y;
    const int b = bl / NLEV, l = bl % NLEV;
    const int A = c_A[l];
    const float2* base2 = (const float2*)(pick(p0, p1, p2, p3, p4, l) + (size_t)b * A * 2);
    const unsigned T = d_T[bl];
    unsigned long long* cand = d_cand + (size_t)bl * SORT_CAP;
    const int lane = threadIdx.x & 31;

    const int chunk = (A + 63) >> 6;
    const int start = blockIdx.x * chunk;
    const int end = min(start + chunk, A);
    const int n = end - start;
    const int rounds = (n + 255) >> 8;
    for (int r = 0; r < rounds; ++r) {
        int i = start + threadIdx.x + (r << 8);
        bool in = i < end;
        unsigned u = 0;
        if (in) u = ordf(base2[i].x);
        bool take = in && (u >= T);
        unsigned m = __ballot_sync(0xffffffffu, take);
        if (m) {
            int leader = __ffs(m) - 1;
            int basep = 0;
            if (lane == leader) basep = atomicAdd(&d_cnt[bl], __popc(m));
            basep = __shfl_sync(0xffffffffu, basep, leader);
            if (take) {
                int p = basep + __popc(m & ((1u << lane) - 1u));
                if (p < SORT_CAP)
                    cand[p] = ((unsigned long long)u << 32) | (unsigned)(~i);
            }
        }
    }
}

// ---------------------------------------------------------------------------
// Kernel 1d: threshold refinement (24-bit) + bitonic sort + decode. (PDL)
// ---------------------------------------------------------------------------
__global__ __launch_bounds__(1024)
void sort_decode_kernel(const float* __restrict__ r0, const float* __restrict__ r1,
                        const float* __restrict__ r2, const float* __restrict__ r3,
                        const float* __restrict__ r4, const float* __restrict__ info) {
    const int bl = blockIdx.x;
    const int b = bl / NLEV, l = bl % NLEV;
    const int K = c_K[l];
    const int tid = threadIdx.x;
    const int lane = tid & 31;

    __shared__ unsigned long long cand[SORT_CAP];   // 32 KB
    __shared__ int h256[256];
    __shared__ int s_c0, s_b2, s_cnt2;
    __shared__ float s_aw[3], s_ah[3];

    if (tid < 3) {
        double rr = (tid == 0) ? 0.5 : ((tid == 1) ? 1.0 : 2.0);
        double sb = (double)c_base[l] * 8.0;
        s_aw[tid] = (float)(sb * sqrt(1.0 / rr));
        s_ah[tid] = (float)(sb * sqrt(rr));
    }
    grid_dep_wait();                 // before reading d_cnt/d_cand

    const unsigned long long* gc = d_cand + (size_t)bl * SORT_CAP;
    const int M = min(d_cnt[bl], SORT_CAP);

    // ---- Refine threshold to 24 bits when the coarse set exceeds 2048 ----
    unsigned Tref = 0;
    if (M > 2048) {
        if (tid < 256) h256[tid] = 0;
        if (tid == 0) s_c0 = 0;
        __syncthreads();
        const unsigned binT = d_T[bl] >> 16;
        const int rounds = (M + 1023) >> 10;
        for (int r = 0; r < rounds; ++r) {
            int i = tid + (r << 10);
            bool in = i < M;
            unsigned u = in ? (unsigned)(gc[i] >> 32) : 0u;
            bool above = in && ((u >> 16) > binT);
            unsigned mb = __ballot_sync(0xffffffffu, above);
            if (lane == 0 && mb) atomicAdd(&s_c0, __popc(mb));
            if (in && ((u >> 16) == binT)) atomicAdd(&h256[(u >> 8) & 0xFFu], 1);
        }
        __syncthreads();
        if (tid == 0) {
            int cum = s_c0, b2 = 0;
            for (int s = 255; s >= 0; --s) {
                cum += h256[s];
                if (cum >= K) { b2 = s; break; }
            }
            s_b2 = b2;
        }
        __syncthreads();
        Tref = (binT << 16) | ((unsigned)s_b2 << 8);
    }

    // ---- Filtered load into smem (warp-aggregated) ----
    if (tid == 0) s_cnt2 = 0;
    __syncthreads();
    {
        const int rounds = (M + 1023) >> 10;
        for (int r = 0; r < rounds; ++r) {
            int i = tid + (r << 10);
            bool in = i < M;
            unsigned long long key = in ? gc[i] : 0ull;
            bool take = in && ((unsigned)(key >> 32) >= Tref);
            int p = warpAppend(&s_cnt2, take);
            if (take && p < SORT_CAP) cand[p] = key;
        }
    }
    __syncthreads();
    const int Muse = min(s_cnt2, SORT_CAP);
    int S = 1024;
    while (S < Muse) S <<= 1;
    for (int i = tid; i < S; i += 1024)
        if (i >= Muse) cand[i] = 0ull;
    __syncthreads();

    // ---- Bitonic sort descending (S keys) ----
    for (int k = 2; k <= S; k <<= 1) {
        for (int j = k >> 1; j > 0; j >>= 1) {
            for (int idx = tid; idx < S; idx += 1024) {
                int ixj = idx ^ j;
                if (ixj > idx) {
                    unsigned long long a = cand[idx], c2 = cand[ixj];
                    bool desc = (idx & k) == 0;
                    if (desc ? (a < c2) : (a > c2)) { cand[idx] = c2; cand[ixj] = a; }
                }
            }
            __syncthreads();
        }
    }

    // ---- Write top-K + inline decode/clip (bit-matching FP) ----
    const float* rg = pick(r0, r1, r2, r3, r4, l);
    const int A = c_A[l];
    const int g = c_grid[l];
    const float strf = (float)c_stride[l];
    const float* in2 = info + b * 3;
    const float H = __fsub_rn(in2[0], 1.0f);
    const float W = __fsub_rn(in2[1], 1.0f);

    for (int j = tid; j < K; j += 1024) {
        unsigned long long key = cand[j];
        const int idx = (int)(~(unsigned)key);
        d_topIdx [bl * PRE_NMS + j] = idx;
        d_topScore[bl * PRE_NMS + j] = iordf((unsigned)(key >> 32));

        const int cell = idx / 3, a = idx - cell * 3;
        const int iy = cell / g, ix = cell - iy * g;

        float cx = __fmul_rn((float)ix + 0.5f, strf);
        float cy = __fmul_rn((float)iy + 0.5f, strf);

        float aw = s_aw[a];
        float ah = s_ah[a];

        float x1a = __fsub_rn(cx, __fmul_rn(0.5f, aw));
        float y1a = __fsub_rn(cy, __fmul_rn(0.5f, ah));
        float x2a = __fadd_rn(cx, __fmul_rn(0.5f, aw));
        float y2a = __fadd_rn(cy, __fmul_rn(0.5f, ah));

        float wa = __fsub_rn(x2a, x1a);
        float ha = __fsub_rn(y2a, y1a);
        float cxa = __fadd_rn(x1a, __fmul_rn(0.5f, wa));
        float cya = __fadd_rn(y1a, __fmul_rn(0.5f, ha));

        const float* rp = rg + ((size_t)b * A + idx) * 4;
        float dx = rp[0], dy = rp[1], dw = rp[2], dh = rp[3];

        float ncx = __fadd_rn(__fmul_rn(dx, wa), cxa);
        float ncy = __fadd_rn(__fmul_rn(dy, ha), cya);
        float nw  = __fmul_rn(expf(dw), wa);
        float nh  = __fmul_rn(expf(dh), ha);

        float x1 = __fsub_rn(ncx, __fmul_rn(0.5f, nw));
        float y1 = __fsub_rn(ncy, __fmul_rn(0.5f, nh));
        float x2 = __fadd_rn(ncx, __fmul_rn(0.5f, nw));
        float y2 = __fadd_rn(ncy, __fmul_rn(0.5f, nh));

        x1 = fminf(fmaxf(x1, 0.0f), W);
        x2 = fminf(fmaxf(x2, 0.0f), W);
        y1 = fminf(fmaxf(y1, 0.0f), H);
        y2 = fminf(fmaxf(y2, 0.0f), H);

        d_topBoxes[bl * PRE_NMS + j] = make_float4(x1, y1, x2, y2);
    }
}

// ---------------------------------------------------------------------------
// Kernel 2: NMS suppression-mask — division-free bracket accept, transposed
// coalesced writes, 2 tiles per 128-thread block. (PDL)
// ---------------------------------------------------------------------------
__global__ __launch_bounds__(128)
void nms_mask_kernel() {
    const int bl = blockIdx.y;
    const int l = bl % NLEV;
    const int N = c_K[l];

    const int grp = threadIdx.x >> 6;      // 0..1
    const int tt  = threadIdx.x & 63;
    const int job = blockIdx.x * MTPB + grp;   // 0..527

    int t = job, y = 0;
    while (t >= NTILE - y) { t -= NTILE - y; ++y; }
    const int x = y + t;

    const int rowStart = y << 6;
    const int colStart = x << 6;
    const bool active = (rowStart < N) && (colStart < N);

    __shared__ float4 cbx[MTPB * 64];
    __shared__ float carea[MTPB * 64];

    grid_dep_wait();                 // before reading d_topBoxes

    if (active) {
        int jj = colStart + tt;
        float4 cj = (jj < N) ? d_topBoxes[bl * PRE_NMS + jj] : make_float4(0.f, 0.f, 0.f, 0.f);
        cbx[(grp << 6) + tt] = cj;
        carea[(grp << 6) + tt] = __fmul_rn(fmaxf(__fsub_rn(cj.z, cj.x), 0.0f),
                                           fmaxf(__fsub_rn(cj.w, cj.y), 0.0f));
    }
    __syncthreads();

    if (!active) return;
    const int i = rowStart + tt;
    if (i >= N) return;
    float4 bi = d_topBoxes[bl * PRE_NMS + i];
    float ai = __fmul_rn(fmaxf(__fsub_rn(bi.z, bi.x), 0.0f),
                         fmaxf(__fsub_rn(bi.w, bi.y), 0.0f));
    unsigned long long bits = 0ull;
    #pragma unroll 8
    for (int jl = 0; jl < 64; ++jl) {
        int jg = colStart + jl;
        if (jg <= i || jg >= N) continue;
        float4 bj = cbx[(grp << 6) + jl];
        float xx1 = fmaxf(bi.x, bj.x), yy1 = fmaxf(bi.y, bj.y);
        float xx2 = fminf(bi.z, bj.z), yy2 = fminf(bi.w, bj.w);
        float w = fmaxf(__fsub_rn(xx2, xx1), 0.0f);
        float h = fmaxf(__fsub_rn(yy2, yy1), 0.0f);
        float inter = __fmul_rn(w, h);
        float aj = carea[(grp << 6) + jl];
        float uni = fmaxf(__fsub_rn(__fadd_rn(ai, aj), inter), 1e-9f);
        float tcut = __fmul_rn(0.7f, uni);
        if (inter > __fmul_rn(tcut, 1.00001f)) {
            bits |= (1ull << jl);                       // definitely IoU > 0.7
        } else if (inter >= __fmul_rn(tcut, 0.99999f)) {
            if (__fdiv_rn(inter, uni) > 0.7f)           // ambiguous band: exact
                bits |= (1ull << jl);
        }
    }
    d_maskT[((size_t)bl * 32 + x) * PRE_NMS + i] = bits;   // coalesced across tt
}

// ---------------------------------------------------------------------------
// Kernel 3: pipelined warp-specialized NMS reduce. (PDL)
// ---------------------------------------------------------------------------
__global__ __launch_bounds__(1024)
void nms_reduce_kernel() {
    grid_dep_wait();
    const int bl = blockIdx.x;
    const int l = bl % NLEV;
    const int N = c_K[l];
    const int KP = c_KP[l];
    const int tid = threadIdx.x;
    const int warp = tid >> 5;
    const int lane = tid & 31;

    __shared__ unsigned long long s_diag[2048];
    __shared__ unsigned long long s_rem[32];
    __shared__ unsigned long long s_keep[32];
    __shared__ int sA[2048], sB[2048];

    const unsigned long long* mT = d_maskT + (size_t)bl * 32 * PRE_NMS;
    const int NC = (N + 63) >> 6;

    for (int i = tid; i < (NC << 6); i += 1024)
        s_diag[i] = (i < N) ? mT[(size_t)(i >> 6) * PRE_NMS + i] : 0ull;
    if (tid < 32) s_rem[tid] = 0ull;
    __syncthreads();

    unsigned long long kreg = 0ull;

    for (int c = 0; c < NC; ++c) {
        const int cc = c + warp;
        const bool doCol = (c > 0) && (cc < NC);
        unsigned long long m0 = 0ull, m1 = 0ull;
        if (doCol) {
            const int rbase = (c - 1) << 6;
            const unsigned long long* colp = mT + (size_t)cc * PRE_NMS + rbase;
            m0 = colp[lane];            // coalesced 256B
            m1 = colp[32 + lane];       // coalesced 256B
        }
        __syncthreads();

        unsigned long long myContrib = 0ull;
        if (doCol) {
            unsigned long long kprev = (warp == 0) ? kreg : s_keep[c - 1];
            unsigned kl = (unsigned)kprev, kh = (unsigned)(kprev >> 32);
            unsigned long long v = 0ull;
            if ((kl >> lane) & 1u) v |= m0;
            if ((kh >> lane) & 1u) v |= m1;
            unsigned vlo = __reduce_or_sync(0xffffffffu, (unsigned)v);
            unsigned vhi = __reduce_or_sync(0xffffffffu, (unsigned)(v >> 32));
            unsigned long long vv = ((unsigned long long)vhi << 32) | vlo;
            if (warp == 0) myContrib = vv;
            else if (lane == 0) s_rem[cc] |= vv;
        }

        if (warp == 0) {
            unsigned long long rem = s_rem[c] | myContrib;
            unsigned rlo = (unsigned)rem, rhi = (unsigned)(rem >> 32);
            unsigned nklo = 0, nkhi = 0;
            const unsigned long long* dg = s_diag + (c << 6);
            #pragma unroll
            for (int k = 0; k < 32; ++k) {
                unsigned s = (unsigned)((int)(rlo << (31 - k)) >> 31);
                unsigned long long m = dg[k];
                rlo |= (unsigned)m & ~s;
                rhi |= (unsigned)(m >> 32) & ~s;
                nklo |= ~s & (1u << k);
            }
            #pragma unroll
            for (int k = 0; k < 32; ++k) {
                unsigned s = (unsigned)((int)(rhi << (31 - k)) >> 31);
                unsigned long long m = dg[32 + k];
                rhi |= (unsigned)(m >> 32) & ~s;
                nkhi |= ~s & (1u << k);
            }
            unsigned long long keepw = ((unsigned long long)nkhi << 32) | nklo;
            const int nr = N - (c << 6);
            if (nr < 64) keepw &= (1ull << nr) - 1ull;
            if (lane == 0) s_keep[c] = keepw;
            kreg = keepw;
        }
    }
    __syncthreads();

    for (int j = tid; j < 2048; j += 1024) {
        int kept = 0;
        if (j < N) kept = (int)((s_keep[j >> 6] >> (j & 63)) & 1ull);
        sA[j] = kept;
    }
    __syncthreads();

    int* src = sA; int* dst = sB;
    for (int off = 1; off < 2048; off <<= 1) {
        for (int j = tid; j < 2048; j += 1024)
            dst[j] = src[j] + ((j >= off) ? src[j - off] : 0);
        __syncthreads();
        int* t = src; src = dst; dst = t;
    }
    const int total = src[2047];

    for (int j = tid; j < N; j += 1024) {
        int kept = (int)((s_keep[j >> 6] >> (j & 63)) & 1ull);
        int incl = src[j];
        if (kept) {
            int rank = incl - 1;
            if (rank < KP) {
                d_lvlScore[bl * POST_NMS + rank] = d_topScore[bl * PRE_NMS + j];
                d_lvlPos  [bl * POST_NMS + rank] = j;
            }
        } else {
            int rank = total + (j - incl);
            if (rank < KP) {
                d_lvlScore[bl * POST_NMS + rank] = -1.0f;
                d_lvlPos  [bl * POST_NMS + rank] = j;
            }
        }
    }
}

// ---------------------------------------------------------------------------
// Kernel 4: final cross-level top-1000 via rank-by-binary-search. (PDL)
// ---------------------------------------------------------------------------
__global__ __launch_bounds__(1024)
void final_kernel(float* __restrict__ out) {
    grid_dep_wait();
    const int b = blockIdx.x;
    const int tid = threadIdx.x;
    __shared__ unsigned long long key[TOTCAT];

    for (int c = tid; c < TOTCAT; c += 1024) {
        int l = (c < 4000) ? (c / 1000) : 4;
        int pos = c - l * 1000;
        float s = d_lvlScore[(b * NLEV + l) * POST_NMS + pos];
        key[c] = ((unsigned long long)ordf(s) << 32) | (unsigned)(~c);
    }
    __syncthreads();

    const int segN[NLEV] = {1000, 1000, 1000, 1000, 768};
    for (int c = tid; c < TOTCAT; c += 1024) {
        unsigned long long ke = key[c];
        int rank = 0;
        #pragma unroll
        for (int l2 = 0; l2 < NLEV; ++l2) {
            const int base2 = l2 * 1000;
            int lo = 0, hi = segN[l2];
            while (lo < hi) {
                int mid = (lo + hi) >> 1;
                if (key[base2 + mid] > ke) lo = mid + 1; else hi = mid;
            }
            rank += lo;
        }
        if (rank < POST_NMS) {
            unsigned hi32 = (unsigned)(ke >> 32);
            int l = (c < 4000) ? (c / 1000) : 4;
            int pos = c - l * 1000;
            float* o = out + ((size_t)b * POST_NMS + rank) * 5;
            o[0] = (float)b;
            if (hi32 & 0x80000000u) {   // score >= 0
                int blx = b * NLEV + l;
                int j = d_lvlPos[blx * POST_NMS + pos];
                float4 bx = d_topBoxes[blx * PRE_NMS + j];
                o[1] = bx.x; o[2] = bx.y; o[3] = bx.z; o[4] = bx.w;
            } else {
                o[1] = 0.0f; o[2] = 0.0f; o[3] = 0.0f; o[4] = 0.0f;
            }
        }
    }
}

// ---------------------------------------------------------------------------
// PDL launch helper
// ---------------------------------------------------------------------------
template <typename F, typename... Args>
static void launch_pdl(dim3 grid, dim3 block, F func, Args... args) {
    cudaLaunchConfig_t cfg = {};
    cfg.gridDim = grid;
    cfg.blockDim = block;
    cfg.dynamicSmemBytes = 0;
    cfg.stream = 0;
    cudaLaunchAttribute attr[1];
    attr[0].id = cudaLaunchAttributeProgrammaticStreamSerialization;
    attr[0].val.programmaticStreamSerializationAllowed = 1;
    cfg.attrs = attr;
    cfg.numAttrs = 1;
    cudaLaunchKernelEx(&cfg, func, args...);
}

// ---------------------------------------------------------------------------
// Launcher — inputs identified BY ELEMENT COUNT (all 11 sizes distinct).
// memset -> hist (normal edge), then 6 PDL-chained kernels.
// ---------------------------------------------------------------------------
extern "C" void kernel_launch(void* const* d_in, const int* in_sizes, int n_in,
                              void* d_out, int out_size) {
    const float* probs[NLEV] = {0, 0, 0, 0, 0};
    const float* regs [NLEV] = {0, 0, 0, 0, 0};
    const float* info = 0;

    for (int i = 0; i < n_in; ++i) {
        const float* p = (const float*)d_in[i];
        switch (in_sizes[i]) {
            case 4 * 196608 * 2: probs[0] = p; break;
            case 4 * 196608 * 4: regs [0] = p; break;
            case 4 * 49152 * 2:  probs[1] = p; break;
            case 4 * 49152 * 4:  regs [1] = p; break;
            case 4 * 12288 * 2:  probs[2] = p; break;
            case 4 * 12288 * 4:  regs [2] = p; break;
            case 4 * 3072 * 2:   probs[3] = p; break;
            case 4 * 3072 * 4:   regs [3] = p; break;
            case 4 * 768 * 2:    probs[4] = p; break;
            case 4 * 768 * 4:    regs [4] = p; break;
            case 12:             info = p; break;
            default: break;
        }
    }
    float* out = (float*)d_out;

    void* histPtr = 0;
    cudaGetSymbolAddress(&histPtr, d_hist);
    cudaMemsetAsync(histPtr, 0, (size_t)NBL * HBINS * sizeof(int));

    hist_kernel<<<dim3(64, NBL), 256>>>(probs[0], probs[1], probs[2], probs[3], probs[4]);
    launch_pdl(dim3(NBL), dim3(1024), select_kernel);
    launch_pdl(dim3(64, NBL), dim3(256), compact_kernel,
               probs[0], probs[1], probs[2], probs[3], probs[4]);
    launch_pdl(dim3(NBL), dim3(1024), sort_decode_kernel,
               regs[0], regs[1], regs[2], regs[3], regs[4], info);
    launch_pdl(dim3(MGRID, NBL), dim3(128), nms_mask_kernel);
    launch_pdl(dim3(NBL), dim3(1024), nms_reduce_kernel);
    launch_pdl(dim3(BATCH), dim3(1024), final_kernel, out);
}

// round 16
// speedup vs baseline: 1.7128x; 1.0054x over previous
#include <cuda_runtime.h>
#include <cstdint>

// ---------------------------------------------------------------------------
// Problem constants
// ---------------------------------------------------------------------------
#define NLEV 5
#define BATCH 4
#define PRE_NMS 2000
#define POST_NMS 1000
#define NBL (BATCH * NLEV)          // 20 (batch, level) pairs
#define SORT_CAP 4096               // max bitonic capacity
#define TOTCAT 4768                 // 4*1000 + 768 concatenated entries
#define HBINS 65536
#define NTILE 32                    // 2000/64 -> 32 tiles
#define NTRI  528                   // 32*33/2 upper-triangle tile pairs
#define MTPB  2                     // mask tiles per block
#define MGRID (NTRI / MTPB)         // 264 mask blocks per bl

__constant__ int c_A[NLEV]      = {196608, 49152, 12288, 3072, 768};
__constant__ int c_K[NLEV]      = {2000, 2000, 2000, 2000, 768};
__constant__ int c_KP[NLEV]     = {1000, 1000, 1000, 1000, 768};
__constant__ int c_stride[NLEV] = {4, 8, 16, 32, 64};
__constant__ int c_grid[NLEV]   = {256, 128, 64, 32, 16};
__constant__ int c_base[NLEV]   = {32, 64, 128, 256, 512};

// ---------------------------------------------------------------------------
// Device scratch (static allocation only)
// ---------------------------------------------------------------------------
__device__ int                 d_hist   [NBL * HBINS];      // 5.2 MB
__device__ unsigned            d_T      [NBL];
__device__ int                 d_cnt    [NBL];
__device__ unsigned long long  d_cand   [NBL * SORT_CAP];
__device__ int                 d_topIdx [NBL * PRE_NMS];
__device__ float               d_topScore[NBL * PRE_NMS];
__device__ float4              d_topBoxes[NBL * PRE_NMS];
__device__ unsigned long long  d_maskT  [NBL * 32 * PRE_NMS];   // [(bl*32+col)*2000+row]
__device__ float               d_lvlScore[NBL * POST_NMS];
__device__ int                 d_lvlPos  [NBL * POST_NMS];

// ---------------------------------------------------------------------------
// Helpers
// ---------------------------------------------------------------------------
__device__ __forceinline__ void grid_dep_wait() {
    asm volatile("griddepcontrol.wait;" ::: "memory");
}
__device__ __forceinline__ unsigned ordf(float f) {
    unsigned u = __float_as_uint(f);
    return (u & 0x80000000u) ? ~u : (u | 0x80000000u);
}
__device__ __forceinline__ float iordf(unsigned u) {
    unsigned v = (u & 0x80000000u) ? (u & 0x7FFFFFFFu) : ~u;
    return __uint_as_float(v);
}
__device__ __forceinline__ const float* pick(const float* a0, const float* a1,
                                             const float* a2, const float* a3,
                                             const float* a4, int l) {
    switch (l) { case 0: return a0; case 1: return a1; case 2: return a2;
                 case 3: return a3; default: return a4; }
}
// Warp-aggregated append; all 32 lanes must execute (use padded loops).
__device__ __forceinline__ int warpAppend(int* ctr, bool pred) {
    unsigned m = __ballot_sync(0xffffffffu, pred);
    int lane = threadIdx.x & 31;
    int base = 0;
    if (m != 0) {
        int leader = __ffs(m) - 1;
        if (lane == leader) base = atomicAdd(ctr, __popc(m));
        base = __shfl_sync(0xffffffffu, base, leader);
    }
    return pred ? base + __popc(m & ((1u << lane) - 1u)) : -1;
}

// ---------------------------------------------------------------------------
// Kernel 1a: parallel 16-bit histogram over ordered score keys.
// ---------------------------------------------------------------------------
__global__ __launch_bounds__(256)
void hist_kernel(const float* __restrict__ p0, const float* __restrict__ p1,
                 const float* __restrict__ p2, const float* __restrict__ p3,
                 const float* __restrict__ p4) {
    const int bl = blockIdx.y;
    const int b = bl / NLEV, l = bl % NLEV;
    const int A = c_A[l];
    const float2* base2 = (const float2*)(pick(p0, p1, p2, p3, p4, l) + (size_t)b * A * 2);
    int* hist = d_hist + (size_t)bl * HBINS;

    const int chunk = (A + 63) >> 6;
    const int start = blockIdx.x * chunk;
    const int end = min(start + chunk, A);
    for (int i = start + threadIdx.x; i < end; i += 256) {
        unsigned u = ordf(base2[i].x);
        atomicAdd(&hist[u >> 16], 1);
    }
}

// ---------------------------------------------------------------------------
// Kernel 1b: per-bl coarse threshold select; also zeroes d_cnt[bl]. (PDL)
// ---------------------------------------------------------------------------
__global__ __launch_bounds__(1024)
void select_kernel() {
    grid_dep_wait();
    const int bl = blockIdx.x;
    const int l = bl % NLEV;
    const int K = c_K[l];
    const int tid = threadIdx.x;
    const int* hist = d_hist + (size_t)bl * HBINS;

    __shared__ int sA[1024], sB[1024];

    if (tid == 0) d_cnt[bl] = 0;

    const int hi = HBINS - 1 - (tid << 6);
    int sum = 0;
    #pragma unroll 8
    for (int k = 0; k < 64; ++k) sum += hist[hi - k];
    sA[tid] = sum;
    __syncthreads();

    int* src = sA; int* dst = sB;
    for (int off = 1; off < 1024; off <<= 1) {
        dst[tid] = src[tid] + ((tid >= off) ? src[tid - off] : 0);
        __syncthreads();
        int* t2 = src; src = dst; dst = t2;
    }

    const int prev = (tid == 0) ? 0 : src[tid - 1];
    if (src[tid] >= K && prev < K) {
        int cum = prev;
        unsigned Tb = 0;
        for (int k = 0; k < 64; ++k) {
            cum += hist[hi - k];
            if (cum >= K) { Tb = (unsigned)(hi - k); break; }
        }
        d_T[bl] = Tb << 16;
    }
}

// ---------------------------------------------------------------------------
// Kernel 1c: parallel compaction of u >= T into per-bl candidate list. (PDL)
// ---------------------------------------------------------------------------
__global__ __launch_bounds__(256)
void compact_kernel(const float* __restrict__ p0, const float* __restrict__ p1,
                    const float* __restrict__ p2, const float* __restrict__ p3,
                    const float* __restrict__ p4) {
    grid_dep_wait();
    const int bl = blockIdx.y;
    const int b = bl / NLEV, l = bl % NLEV;
    const int A = c_A[l];
    const float2* base2 = (const float2*)(pick(p0, p1, p2, p3, p4, l) + (size_t)b * A * 2);
    const unsigned T = d_T[bl];
    unsigned long long* cand = d_cand + (size_t)bl * SORT_CAP;
    const int lane = threadIdx.x & 31;

    const int chunk = (A + 63) >> 6;
    const int start = blockIdx.x * chunk;
    const int end = min(start + chunk, A);
    const int n = end - start;
    const int rounds = (n + 255) >> 8;
    for (int r = 0; r < rounds; ++r) {
        int i = start + threadIdx.x + (r << 8);
        bool in = i < end;
        unsigned u = 0;
        if (in) u = ordf(base2[i].x);
        bool take = in && (u >= T);
        unsigned m = __ballot_sync(0xffffffffu, take);
        if (m) {
            int leader = __ffs(m) - 1;
            int basep = 0;
            if (lane == leader) basep = atomicAdd(&d_cnt[bl], __popc(m));
            basep = __shfl_sync(0xffffffffu, basep, leader);
            if (take) {
                int p = basep + __popc(m & ((1u << lane) - 1u));
                if (p < SORT_CAP)
                    cand[p] = ((unsigned long long)u << 32) | (unsigned)(~i);
            }
        }
    }
}

// ---------------------------------------------------------------------------
// Kernel 1d: threshold refinement (24-bit) + bitonic sort + decode. (PDL)
// Bitonic sort: __syncwarp for strides j<32 (warp-local exchanges),
// __syncthreads only after cross-warp phases (j>=32).
// ---------------------------------------------------------------------------
__global__ __launch_bounds__(1024)
void sort_decode_kernel(const float* __restrict__ r0, const float* __restrict__ r1,
                        const float* __restrict__ r2, const float* __restrict__ r3,
                        const float* __restrict__ r4, const float* __restrict__ info) {
    const int bl = blockIdx.x;
    const int b = bl / NLEV, l = bl % NLEV;
    const int K = c_K[l];
    const int tid = threadIdx.x;
    const int lane = tid & 31;

    __shared__ unsigned long long cand[SORT_CAP];   // 32 KB
    __shared__ int h256[256];
    __shared__ int s_c0, s_b2, s_cnt2;
    __shared__ float s_aw[3], s_ah[3];

    if (tid < 3) {
        double rr = (tid == 0) ? 0.5 : ((tid == 1) ? 1.0 : 2.0);
        double sb = (double)c_base[l] * 8.0;
        s_aw[tid] = (float)(sb * sqrt(1.0 / rr));
        s_ah[tid] = (float)(sb * sqrt(rr));
    }
    grid_dep_wait();                 // before reading d_cnt/d_cand

    const unsigned long long* gc = d_cand + (size_t)bl * SORT_CAP;
    const int M = min(d_cnt[bl], SORT_CAP);

    // ---- Refine threshold to 24 bits when the coarse set exceeds 2048 ----
    unsigned Tref = 0;
    if (M > 2048) {
        if (tid < 256) h256[tid] = 0;
        if (tid == 0) s_c0 = 0;
        __syncthreads();
        const unsigned binT = d_T[bl] >> 16;
        const int rounds = (M + 1023) >> 10;
        for (int r = 0; r < rounds; ++r) {
            int i = tid + (r << 10);
            bool in = i < M;
            unsigned u = in ? (unsigned)(gc[i] >> 32) : 0u;
            bool above = in && ((u >> 16) > binT);
            unsigned mb = __ballot_sync(0xffffffffu, above);
            if (lane == 0 && mb) atomicAdd(&s_c0, __popc(mb));
            if (in && ((u >> 16) == binT)) atomicAdd(&h256[(u >> 8) & 0xFFu], 1);
        }
        __syncthreads();
        if (tid == 0) {
            int cum = s_c0, b2 = 0;
            for (int s = 255; s >= 0; --s) {
                cum += h256[s];
                if (cum >= K) { b2 = s; break; }
            }
            s_b2 = b2;
        }
        __syncthreads();
        Tref = (binT << 16) | ((unsigned)s_b2 << 8);
    }

    // ---- Filtered load into smem (warp-aggregated) ----
    if (tid == 0) s_cnt2 = 0;
    __syncthreads();
    {
        const int rounds = (M + 1023) >> 10;
        for (int r = 0; r < rounds; ++r) {
            int i = tid + (r << 10);
            bool in = i < M;
            unsigned long long key = in ? gc[i] : 0ull;
            bool take = in && ((unsigned)(key >> 32) >= Tref);
            int p = warpAppend(&s_cnt2, take);
            if (take && p < SORT_CAP) cand[p] = key;
        }
    }
    __syncthreads();
    const int Muse = min(s_cnt2, SORT_CAP);
    int S = 1024;
    while (S < Muse) S <<= 1;
    for (int i = tid; i < S; i += 1024)
        if (i >= Muse) cand[i] = 0ull;
    __syncthreads();

    // ---- Bitonic sort descending (S keys), hybrid barrier granularity ----
    for (int k = 2; k <= S; k <<= 1) {
        for (int j = k >> 1; j > 0; j >>= 1) {
            for (int idx = tid; idx < S; idx += 1024) {
                int ixj = idx ^ j;
                if (ixj > idx) {
                    unsigned long long a = cand[idx], c2 = cand[ixj];
                    bool desc = (idx & k) == 0;
                    if (desc ? (a < c2) : (a > c2)) { cand[idx] = c2; cand[ixj] = a; }
                }
            }
            if (j >= 32) __syncthreads();
            else         __syncwarp();
        }
    }
    __syncthreads();   // publish warp-local tail phases before cross-warp reads

    // ---- Write top-K + inline decode/clip (bit-matching FP) ----
    const float* rg = pick(r0, r1, r2, r3, r4, l);
    const int A = c_A[l];
    const int g = c_grid[l];
    const float strf = (float)c_stride[l];
    const float* in2 = info + b * 3;
    const float H = __fsub_rn(in2[0], 1.0f);
    const float W = __fsub_rn(in2[1], 1.0f);

    for (int j = tid; j < K; j += 1024) {
        unsigned long long key = cand[j];
        const int idx = (int)(~(unsigned)key);
        d_topIdx [bl * PRE_NMS + j] = idx;
        d_topScore[bl * PRE_NMS + j] = iordf((unsigned)(key >> 32));

        const int cell = idx / 3, a = idx - cell * 3;
        const int iy = cell / g, ix = cell - iy * g;

        float cx = __fmul_rn((float)ix + 0.5f, strf);
        float cy = __fmul_rn((float)iy + 0.5f, strf);

        float aw = s_aw[a];
        float ah = s_ah[a];

        float x1a = __fsub_rn(cx, __fmul_rn(0.5f, aw));
        float y1a = __fsub_rn(cy, __fmul_rn(0.5f, ah));
        float x2a = __fadd_rn(cx, __fmul_rn(0.5f, aw));
        float y2a = __fadd_rn(cy, __fmul_rn(0.5f, ah));

        float wa = __fsub_rn(x2a, x1a);
        float ha = __fsub_rn(y2a, y1a);
        float cxa = __fadd_rn(x1a, __fmul_rn(0.5f, wa));
        float cya = __fadd_rn(y1a, __fmul_rn(0.5f, ha));

        const float* rp = rg + ((size_t)b * A + idx) * 4;
        float dx = rp[0], dy = rp[1], dw = rp[2], dh = rp[3];

        float ncx = __fadd_rn(__fmul_rn(dx, wa), cxa);
        float ncy = __fadd_rn(__fmul_rn(dy, ha), cya);
        float nw  = __fmul_rn(expf(dw), wa);
        float nh  = __fmul_rn(expf(dh), ha);

        float x1 = __fsub_rn(ncx, __fmul_rn(0.5f, nw));
        float y1 = __fsub_rn(ncy, __fmul_rn(0.5f, nh));
        float x2 = __fadd_rn(ncx, __fmul_rn(0.5f, nw));
        float y2 = __fadd_rn(ncy, __fmul_rn(0.5f, nh));

        x1 = fminf(fmaxf(x1, 0.0f), W);
        x2 = fminf(fmaxf(x2, 0.0f), W);
        y1 = fminf(fmaxf(y1, 0.0f), H);
        y2 = fminf(fmaxf(y2, 0.0f), H);

        d_topBoxes[bl * PRE_NMS + j] = make_float4(x1, y1, x2, y2);
    }
}

// ---------------------------------------------------------------------------
// Kernel 2: NMS suppression-mask — division-free bracket accept, transposed
// coalesced writes, 2 tiles per 128-thread block. (PDL)
// ---------------------------------------------------------------------------
__global__ __launch_bounds__(128)
void nms_mask_kernel() {
    const int bl = blockIdx.y;
    const int l = bl % NLEV;
    const int N = c_K[l];

    const int grp = threadIdx.x >> 6;      // 0..1
    const int tt  = threadIdx.x & 63;
    const int job = blockIdx.x * MTPB + grp;   // 0..527

    int t = job, y = 0;
    while (t >= NTILE - y) { t -= NTILE - y; ++y; }
    const int x = y + t;

    const int rowStart = y << 6;
    const int colStart = x << 6;
    const bool active = (rowStart < N) && (colStart < N);

    __shared__ float4 cbx[MTPB * 64];
    __shared__ float carea[MTPB * 64];

    grid_dep_wait();                 // before reading d_topBoxes

    if (active) {
        int jj = colStart + tt;
        float4 cj = (jj < N) ? d_topBoxes[bl * PRE_NMS + jj] : make_float4(0.f, 0.f, 0.f, 0.f);
        cbx[(grp << 6) + tt] = cj;
        carea[(grp << 6) + tt] = __fmul_rn(fmaxf(__fsub_rn(cj.z, cj.x), 0.0f),
                                           fmaxf(__fsub_rn(cj.w, cj.y), 0.0f));
    }
    __syncthreads();

    if (!active) return;
    const int i = rowStart + tt;
    if (i >= N) return;
    float4 bi = d_topBoxes[bl * PRE_NMS + i];
    float ai = __fmul_rn(fmaxf(__fsub_rn(bi.z, bi.x), 0.0f),
                         fmaxf(__fsub_rn(bi.w, bi.y), 0.0f));
    unsigned long long bits = 0ull;
    #pragma unroll 8
    for (int jl = 0; jl < 64; ++jl) {
        int jg = colStart + jl;
        if (jg <= i || jg >= N) continue;
        float4 bj = cbx[(grp << 6) + jl];
        float xx1 = fmaxf(bi.x, bj.x), yy1 = fmaxf(bi.y, bj.y);
        float xx2 = fminf(bi.z, bj.z), yy2 = fminf(bi.w, bj.w);
        float w = fmaxf(__fsub_rn(xx2, xx1), 0.0f);
        float h = fmaxf(__fsub_rn(yy2, yy1), 0.0f);
        float inter = __fmul_rn(w, h);
        float aj = carea[(grp << 6) + jl];
        float uni = fmaxf(__fsub_rn(__fadd_rn(ai, aj), inter), 1e-9f);
        float tcut = __fmul_rn(0.7f, uni);
        if (inter > __fmul_rn(tcut, 1.00001f)) {
            bits |= (1ull << jl);                       // definitely IoU > 0.7
        } else if (inter >= __fmul_rn(tcut, 0.99999f)) {
            if (__fdiv_rn(inter, uni) > 0.7f)           // ambiguous band: exact
                bits |= (1ull << jl);
        }
    }
    d_maskT[((size_t)bl * 32 + x) * PRE_NMS + i] = bits;   // coalesced across tt
}

// ---------------------------------------------------------------------------
// Kernel 3: pipelined warp-specialized NMS reduce. (PDL)
// Early-skip of the serial chain when a chunk is already fully suppressed.
// ---------------------------------------------------------------------------
__global__ __launch_bounds__(1024)
void nms_reduce_kernel() {
    grid_dep_wait();
    const int bl = blockIdx.x;
    const int l = bl % NLEV;
    const int N = c_K[l];
    const int KP = c_KP[l];
    const int tid = threadIdx.x;
    const int warp = tid >> 5;
    const int lane = tid & 31;

    __shared__ unsigned long long s_diag[2048];
    __shared__ unsigned long long s_rem[32];
    __shared__ unsigned long long s_keep[32];
    __shared__ int sA[2048], sB[2048];

    const unsigned long long* mT = d_maskT + (size_t)bl * 32 * PRE_NMS;
    const int NC = (N + 63) >> 6;

    for (int i = tid; i < (NC << 6); i += 1024)
        s_diag[i] = (i < N) ? mT[(size_t)(i >> 6) * PRE_NMS + i] : 0ull;
    if (tid < 32) s_rem[tid] = 0ull;
    __syncthreads();

    unsigned long long kreg = 0ull;

    for (int c = 0; c < NC; ++c) {
        const int cc = c + warp;
        const bool doCol = (c > 0) && (cc < NC);
        unsigned long long m0 = 0ull, m1 = 0ull;
        if (doCol) {
            const int rbase = (c - 1) << 6;
            const unsigned long long* colp = mT + (size_t)cc * PRE_NMS + rbase;
            m0 = colp[lane];            // coalesced 256B
            m1 = colp[32 + lane];       // coalesced 256B
        }
        __syncthreads();

        unsigned long long myContrib = 0ull;
        if (doCol) {
            unsigned long long kprev = (warp == 0) ? kreg : s_keep[c - 1];
            unsigned kl = (unsigned)kprev, kh = (unsigned)(kprev >> 32);
            unsigned long long v = 0ull;
            if ((kl >> lane) & 1u) v |= m0;
            if ((kh >> lane) & 1u) v |= m1;
            unsigned vlo = __reduce_or_sync(0xffffffffu, (unsigned)v);
            unsigned vhi = __reduce_or_sync(0xffffffffu, (unsigned)(v >> 32));
            unsigned long long vv = ((unsigned long long)vhi << 32) | vlo;
            if (warp == 0) myContrib = vv;
            else if (lane == 0) s_rem[cc] |= vv;
        }

        if (warp == 0) {
            unsigned long long rem = s_rem[c] | myContrib;
            unsigned rlo = (unsigned)rem, rhi = (unsigned)(rem >> 32);
            unsigned long long keepw;
            if ((rlo & rhi) == 0xFFFFFFFFu) {
                keepw = 0ull;                       // chunk fully suppressed
            } else {
                unsigned nklo = 0, nkhi = 0;
                const unsigned long long* dg = s_diag + (c << 6);
                #pragma unroll
                for (int k = 0; k < 32; ++k) {
                    unsigned s = (unsigned)((int)(rlo << (31 - k)) >> 31);
                    unsigned long long m = dg[k];
                    rlo |= (unsigned)m & ~s;
                    rhi |= (unsigned)(m >> 32) & ~s;
                    nklo |= ~s & (1u << k);
                }
                #pragma unroll
                for (int k = 0; k < 32; ++k) {
                    unsigned s = (unsigned)((int)(rhi << (31 - k)) >> 31);
                    unsigned long long m = dg[32 + k];
                    rhi |= (unsigned)(m >> 32) & ~s;
                    nkhi |= ~s & (1u << k);
                }
                keepw = ((unsigned long long)nkhi << 32) | nklo;
                const int nr = N - (c << 6);
                if (nr < 64) keepw &= (1ull << nr) - 1ull;
            }
            if (lane == 0) s_keep[c] = keepw;
            kreg = keepw;
        }
    }
    __syncthreads();

    for (int j = tid; j < 2048; j += 1024) {
        int kept = 0;
        if (j < N) kept = (int)((s_keep[j >> 6] >> (j & 63)) & 1ull);
        sA[j] = kept;
    }
    __syncthreads();

    int* src = sA; int* dst = sB;
    for (int off = 1; off < 2048; off <<= 1) {
        for (int j = tid; j < 2048; j += 1024)
            dst[j] = src[j] + ((j >= off) ? src[j - off] : 0);
        __syncthreads();
        int* t = src; src = dst; dst = t;
    }
    const int total = src[2047];

    for (int j = tid; j < N; j += 1024) {
        int kept = (int)((s_keep[j >> 6] >> (j & 63)) & 1ull);
        int incl = src[j];
        if (kept) {
            int rank = incl - 1;
            if (rank < KP) {
                d_lvlScore[bl * POST_NMS + rank] = d_topScore[bl * PRE_NMS + j];
                d_lvlPos  [bl * POST_NMS + rank] = j;
            }
        } else {
            int rank = total + (j - incl);
            if (rank < KP) {
                d_lvlScore[bl * POST_NMS + rank] = -1.0f;
                d_lvlPos  [bl * POST_NMS + rank] = j;
            }
        }
    }
}

// ---------------------------------------------------------------------------
// Kernel 4: final cross-level top-1000 via rank-by-binary-search. (PDL)
// ---------------------------------------------------------------------------
__global__ __launch_bounds__(1024)
void final_kernel(float* __restrict__ out) {
    grid_dep_wait();
    const int b = blockIdx.x;
    const int tid = threadIdx.x;
    __shared__ unsigned long long key[TOTCAT];

    for (int c = tid; c < TOTCAT; c += 1024) {
        int l = (c < 4000) ? (c / 1000) : 4;
        int pos = c - l * 1000;
        float s = d_lvlScore[(b * NLEV + l) * POST_NMS + pos];
        key[c] = ((unsigned long long)ordf(s) << 32) | (unsigned)(~c);
    }
    __syncthreads();

    const int segN[NLEV] = {1000, 1000, 1000, 1000, 768};
    for (int c = tid; c < TOTCAT; c += 1024) {
        unsigned long long ke = key[c];
        int rank = 0;
        #pragma unroll
        for (int l2 = 0; l2 < NLEV; ++l2) {
            const int base2 = l2 * 1000;
            int lo = 0, hi = segN[l2];
            while (lo < hi) {
                int mid = (lo + hi) >> 1;
                if (key[base2 + mid] > ke) lo = mid + 1; else hi = mid;
            }
            rank += lo;
        }
        if (rank < POST_NMS) {
            unsigned hi32 = (unsigned)(ke >> 32);
            int l = (c < 4000) ? (c / 1000) : 4;
            int pos = c - l * 1000;
            float* o = out + ((size_t)b * POST_NMS + rank) * 5;
            o[0] = (float)b;
            if (hi32 & 0x80000000u) {   // score >= 0
                int blx = b * NLEV + l;
                int j = d_lvlPos[blx * POST_NMS + pos];
                float4 bx = d_topBoxes[blx * PRE_NMS + j];
                o[1] = bx.x; o[2] = bx.y; o[3] = bx.z; o[4] = bx.w;
            } else {
                o[1] = 0.0f; o[2] = 0.0f; o[3] = 0.0f; o[4] = 0.0f;
            }
        }
    }
}

// ---------------------------------------------------------------------------
// PDL launch helper
// ---------------------------------------------------------------------------
template <typename F, typename... Args>
static void launch_pdl(dim3 grid, dim3 block, F func, Args... args) {
    cudaLaunchConfig_t cfg = {};
    cfg.gridDim = grid;
    cfg.blockDim = block;
    cfg.dynamicSmemBytes = 0;
    cfg.stream = 0;
    cudaLaunchAttribute attr[1];
    attr[0].id = cudaLaunchAttributeProgrammaticStreamSerialization;
    attr[0].val.programmaticStreamSerializationAllowed = 1;
    cfg.attrs = attr;
    cfg.numAttrs = 1;
    cudaLaunchKernelEx(&cfg, func, args...);
}

// ---------------------------------------------------------------------------
// Launcher — inputs identified BY ELEMENT COUNT (all 11 sizes distinct).
// ---------------------------------------------------------------------------
extern "C" void kernel_launch(void* const* d_in, const int* in_sizes, int n_in,
                              void* d_out, int out_size) {
    const float* probs[NLEV] = {0, 0, 0, 0, 0};
    const float* regs [NLEV] = {0, 0, 0, 0, 0};
    const float* info = 0;

    for (int i = 0; i < n_in; ++i) {
        const float* p = (const float*)d_in[i];
        switch (in_sizes[i]) {
            case 4 * 196608 * 2: probs[0] = p; break;
            case 4 * 196608 * 4: regs [0] = p; break;
            case 4 * 49152 * 2:  probs[1] = p; break;
            case 4 * 49152 * 4:  regs [1] = p; break;
            case 4 * 12288 * 2:  probs[2] = p; break;
            case 4 * 12288 * 4:  regs [2] = p; break;
            case 4 * 3072 * 2:   probs[3] = p; break;
            case 4 * 3072 * 4:   regs [3] = p; break;
            case 4 * 768 * 2:    probs[4] = p; break;
            case 4 * 768 * 4:    regs [4] = p; break;
            case 12:             info = p; break;
            default: break;
        }
    }
    float* out = (float*)d_out;

    void* histPtr = 0;
    cudaGetSymbolAddress(&histPtr, d_hist);
    cudaMemsetAsync(histPtr, 0, (size_t)NBL * HBINS * sizeof(int));

    hist_kernel<<<dim3(64, NBL), 256>>>(probs[0], probs[1], probs[2], probs[3], probs[4]);
    launch_pdl(dim3(NBL), dim3(1024), select_kernel);
    launch_pdl(dim3(64, NBL), dim3(256), compact_kernel,
               probs[0], probs[1], probs[2], probs[3], probs[4]);
    launch_pdl(dim3(NBL), dim3(1024), sort_decode_kernel,
               regs[0], regs[1], regs[2], regs[3], regs[4], info);
    launch_pdl(dim3(MGRID, NBL), dim3(128), nms_mask_kernel);
    launch_pdl(dim3(NBL), dim3(1024), nms_reduce_kernel);
    launch_pdl(dim3(BATCH), dim3(1024), final_kernel, out);
}

// round 17
// speedup vs baseline: 1.7324x; 1.0114x over previous
#include <cuda_runtime.h>
#include <cstdint>

// ---------------------------------------------------------------------------
// Problem constants
// ---------------------------------------------------------------------------
#define NLEV 5
#define BATCH 4
#define PRE_NMS 2000
#define POST_NMS 1000
#define NBL (BATCH * NLEV)          // 20 (batch, level) pairs
#define NBL_H (NBL / 2)             // 10 per chain
#define SORT_CAP 4096
#define TOTCAT 4768
#define HBINS 65536
#define NTILE 32
#define NTRI  528
#define MTPB  2
#define MGRID (NTRI / MTPB)         // 264 mask blocks per bl

__constant__ int c_A[NLEV]      = {196608, 49152, 12288, 3072, 768};
__constant__ int c_K[NLEV]      = {2000, 2000, 2000, 2000, 768};
__constant__ int c_KP[NLEV]     = {1000, 1000, 1000, 1000, 768};
__constant__ int c_stride[NLEV] = {4, 8, 16, 32, 64};
__constant__ int c_grid[NLEV]   = {256, 128, 64, 32, 16};
__constant__ int c_base[NLEV]   = {32, 64, 128, 256, 512};

// ---------------------------------------------------------------------------
// Device scratch (static allocation only)
// ---------------------------------------------------------------------------
__device__ int                 d_hist   [NBL * HBINS];      // 5.2 MB
__device__ unsigned            d_T      [NBL];
__device__ int                 d_cnt    [NBL];
__device__ unsigned long long  d_cand   [NBL * SORT_CAP];
__device__ int                 d_topIdx [NBL * PRE_NMS];
__device__ float               d_topScore[NBL * PRE_NMS];
__device__ float4              d_topBoxes[NBL * PRE_NMS];
__device__ unsigned long long  d_maskT  [NBL * 32 * PRE_NMS];
__device__ float               d_lvlScore[NBL * POST_NMS];
__device__ int                 d_lvlPos  [NBL * POST_NMS];

// ---------------------------------------------------------------------------
// Helpers
// ---------------------------------------------------------------------------
__device__ __forceinline__ void grid_dep_wait() {
    asm volatile("griddepcontrol.wait;" ::: "memory");
}
__device__ __forceinline__ unsigned ordf(float f) {
    unsigned u = __float_as_uint(f);
    return (u & 0x80000000u) ? ~u : (u | 0x80000000u);
}
__device__ __forceinline__ float iordf(unsigned u) {
    unsigned v = (u & 0x80000000u) ? (u & 0x7FFFFFFFu) : ~u;
    return __uint_as_float(v);
}
__device__ __forceinline__ const float* pick(const float* a0, const float* a1,
                                             const float* a2, const float* a3,
                                             const float* a4, int l) {
    switch (l) { case 0: return a0; case 1: return a1; case 2: return a2;
                 case 3: return a3; default: return a4; }
}
__device__ __forceinline__ int warpAppend(int* ctr, bool pred) {
    unsigned m = __ballot_sync(0xffffffffu, pred);
    int lane = threadIdx.x & 31;
    int base = 0;
    if (m != 0) {
        int leader = __ffs(m) - 1;
        if (lane == leader) base = atomicAdd(ctr, __popc(m));
        base = __shfl_sync(0xffffffffu, base, leader);
    }
    return pred ? base + __popc(m & ((1u << lane) - 1u)) : -1;
}

// ---------------------------------------------------------------------------
// Kernel 1a: parallel 16-bit histogram (half-chain: bl = blBase+blockIdx.y)
// ---------------------------------------------------------------------------
__global__ __launch_bounds__(256)
void hist_kernel(const float* __restrict__ p0, const float* __restrict__ p1,
                 const float* __restrict__ p2, const float* __restrict__ p3,
                 const float* __restrict__ p4, int blBase) {
    const int bl = blBase + blockIdx.y;
    const int b = bl / NLEV, l = bl % NLEV;
    const int A = c_A[l];
    const float2* base2 = (const float2*)(pick(p0, p1, p2, p3, p4, l) + (size_t)b * A * 2);
    int* hist = d_hist + (size_t)bl * HBINS;

    const int chunk = (A + 63) >> 6;
    const int start = blockIdx.x * chunk;
    const int end = min(start + chunk, A);
    for (int i = start + threadIdx.x; i < end; i += 256) {
        unsigned u = ordf(base2[i].x);
        atomicAdd(&hist[u >> 16], 1);
    }
}

// ---------------------------------------------------------------------------
// Kernel 1b: coarse threshold select; zeroes d_cnt[bl]. (PDL)
// ---------------------------------------------------------------------------
__global__ __launch_bounds__(1024)
void select_kernel(int blBase) {
    grid_dep_wait();
    const int bl = blBase + blockIdx.x;
    const int l = bl % NLEV;
    const int K = c_K[l];
    const int tid = threadIdx.x;
    const int* hist = d_hist + (size_t)bl * HBINS;

    __shared__ int sA[1024], sB[1024];

    if (tid == 0) d_cnt[bl] = 0;

    const int hi = HBINS - 1 - (tid << 6);
    int sum = 0;
    #pragma unroll 8
    for (int k = 0; k < 64; ++k) sum += hist[hi - k];
    sA[tid] = sum;
    __syncthreads();

    int* src = sA; int* dst = sB;
    for (int off = 1; off < 1024; off <<= 1) {
        dst[tid] = src[tid] + ((tid >= off) ? src[tid - off] : 0);
        __syncthreads();
        int* t2 = src; src = dst; dst = t2;
    }

    const int prev = (tid == 0) ? 0 : src[tid - 1];
    if (src[tid] >= K && prev < K) {
        int cum = prev;
        unsigned Tb = 0;
        for (int k = 0; k < 64; ++k) {
            cum += hist[hi - k];
            if (cum >= K) { Tb = (unsigned)(hi - k); break; }
        }
        d_T[bl] = Tb << 16;
    }
}

// ---------------------------------------------------------------------------
// Kernel 1c: compaction of u >= T. (PDL)
// ---------------------------------------------------------------------------
__global__ __launch_bounds__(256)
void compact_kernel(const float* __restrict__ p0, const float* __restrict__ p1,
                    const float* __restrict__ p2, const float* __restrict__ p3,
                    const float* __restrict__ p4, int blBase) {
    grid_dep_wait();
    const int bl = blBase + blockIdx.y;
    const int b = bl / NLEV, l = bl % NLEV;
    const int A = c_A[l];
    const float2* base2 = (const float2*)(pick(p0, p1, p2, p3, p4, l) + (size_t)b * A * 2);
    const unsigned T = d_T[bl];
    unsigned long long* cand = d_cand + (size_t)bl * SORT_CAP;
    const int lane = threadIdx.x & 31;

    const int chunk = (A + 63) >> 6;
    const int start = blockIdx.x * chunk;
    const int end = min(start + chunk, A);
    const int n = end - start;
    const int rounds = (n + 255) >> 8;
    for (int r = 0; r < rounds; ++r) {
        int i = start + threadIdx.x + (r << 8);
        bool in = i < end;
        unsigned u = 0;
        if (in) u = ordf(base2[i].x);
        bool take = in && (u >= T);
        unsigned m = __ballot_sync(0xffffffffu, take);
        if (m) {
            int leader = __ffs(m) - 1;
            int basep = 0;
            if (lane == leader) basep = atomicAdd(&d_cnt[bl], __popc(m));
            basep = __shfl_sync(0xffffffffu, basep, leader);
            if (take) {
                int p = basep + __popc(m & ((1u << lane) - 1u));
                if (p < SORT_CAP)
                    cand[p] = ((unsigned long long)u << 32) | (unsigned)(~i);
            }
        }
    }
}

// ---------------------------------------------------------------------------
// Kernel 1d: refinement + hybrid-barrier bitonic sort + decode. (PDL)
// ---------------------------------------------------------------------------
__global__ __launch_bounds__(1024)
void sort_decode_kernel(const float* __restrict__ r0, const float* __restrict__ r1,
                        const float* __restrict__ r2, const float* __restrict__ r3,
                        const float* __restrict__ r4, const float* __restrict__ info,
                        int blBase) {
    const int bl = blBase + blockIdx.x;
    const int b = bl / NLEV, l = bl % NLEV;
    const int K = c_K[l];
    const int tid = threadIdx.x;
    const int lane = tid & 31;

    __shared__ unsigned long long cand[SORT_CAP];   // 32 KB
    __shared__ int h256[256];
    __shared__ int s_c0, s_b2, s_cnt2;
    __shared__ float s_aw[3], s_ah[3];

    if (tid < 3) {
        double rr = (tid == 0) ? 0.5 : ((tid == 1) ? 1.0 : 2.0);
        double sb = (double)c_base[l] * 8.0;
        s_aw[tid] = (float)(sb * sqrt(1.0 / rr));
        s_ah[tid] = (float)(sb * sqrt(rr));
    }
    grid_dep_wait();

    const unsigned long long* gc = d_cand + (size_t)bl * SORT_CAP;
    const int M = min(d_cnt[bl], SORT_CAP);

    unsigned Tref = 0;
    if (M > 2048) {
        if (tid < 256) h256[tid] = 0;
        if (tid == 0) s_c0 = 0;
        __syncthreads();
        const unsigned binT = d_T[bl] >> 16;
        const int rounds = (M + 1023) >> 10;
        for (int r = 0; r < rounds; ++r) {
            int i = tid + (r << 10);
            bool in = i < M;
            unsigned u = in ? (unsigned)(gc[i] >> 32) : 0u;
            bool above = in && ((u >> 16) > binT);
            unsigned mb = __ballot_sync(0xffffffffu, above);
            if (lane == 0 && mb) atomicAdd(&s_c0, __popc(mb));
            if (in && ((u >> 16) == binT)) atomicAdd(&h256[(u >> 8) & 0xFFu], 1);
        }
        __syncthreads();
        if (tid == 0) {
            int cum = s_c0, b2 = 0;
            for (int s = 255; s >= 0; --s) {
                cum += h256[s];
                if (cum >= K) { b2 = s; break; }
            }
            s_b2 = b2;
        }
        __syncthreads();
        Tref = (binT << 16) | ((unsigned)s_b2 << 8);
    }

    if (tid == 0) s_cnt2 = 0;
    __syncthreads();
    {
        const int rounds = (M + 1023) >> 10;
        for (int r = 0; r < rounds; ++r) {
            int i = tid + (r << 10);
            bool in = i < M;
            unsigned long long key = in ? gc[i] : 0ull;
            bool take = in && ((unsigned)(key >> 32) >= Tref);
            int p = warpAppend(&s_cnt2, take);
            if (take && p < SORT_CAP) cand[p] = key;
        }
    }
    __syncthreads();
    const int Muse = min(s_cnt2, SORT_CAP);
    int S = 1024;
    while (S < Muse) S <<= 1;
    for (int i = tid; i < S; i += 1024)
        if (i >= Muse) cand[i] = 0ull;
    __syncthreads();

    for (int k = 2; k <= S; k <<= 1) {
        for (int j = k >> 1; j > 0; j >>= 1) {
            for (int idx = tid; idx < S; idx += 1024) {
                int ixj = idx ^ j;
                if (ixj > idx) {
                    unsigned long long a = cand[idx], c2 = cand[ixj];
                    bool desc = (idx & k) == 0;
                    if (desc ? (a < c2) : (a > c2)) { cand[idx] = c2; cand[ixj] = a; }
                }
            }
            if (j >= 32) __syncthreads();
            else         __syncwarp();
        }
    }
    __syncthreads();

    const float* rg = pick(r0, r1, r2, r3, r4, l);
    const int A = c_A[l];
    const int g = c_grid[l];
    const float strf = (float)c_stride[l];
    const float* in2 = info + b * 3;
    const float H = __fsub_rn(in2[0], 1.0f);
    const float W = __fsub_rn(in2[1], 1.0f);

    for (int j = tid; j < K; j += 1024) {
        unsigned long long key = cand[j];
        const int idx = (int)(~(unsigned)key);
        d_topIdx [bl * PRE_NMS + j] = idx;
        d_topScore[bl * PRE_NMS + j] = iordf((unsigned)(key >> 32));

        const int cell = idx / 3, a = idx - cell * 3;
        const int iy = cell / g, ix = cell - iy * g;

        float cx = __fmul_rn((float)ix + 0.5f, strf);
        float cy = __fmul_rn((float)iy + 0.5f, strf);

        float aw = s_aw[a];
        float ah = s_ah[a];

        float x1a = __fsub_rn(cx, __fmul_rn(0.5f, aw));
        float y1a = __fsub_rn(cy, __fmul_rn(0.5f, ah));
        float x2a = __fadd_rn(cx, __fmul_rn(0.5f, aw));
        float y2a = __fadd_rn(cy, __fmul_rn(0.5f, ah));

        float wa = __fsub_rn(x2a, x1a);
        float ha = __fsub_rn(y2a, y1a);
        float cxa = __fadd_rn(x1a, __fmul_rn(0.5f, wa));
        float cya = __fadd_rn(y1a, __fmul_rn(0.5f, ha));

        const float* rp = rg + ((size_t)b * A + idx) * 4;
        float dx = rp[0], dy = rp[1], dw = rp[2], dh = rp[3];

        float ncx = __fadd_rn(__fmul_rn(dx, wa), cxa);
        float ncy = __fadd_rn(__fmul_rn(dy, ha), cya);
        float nw  = __fmul_rn(expf(dw), wa);
        float nh  = __fmul_rn(expf(dh), ha);

        float x1 = __fsub_rn(ncx, __fmul_rn(0.5f, nw));
        float y1 = __fsub_rn(ncy, __fmul_rn(0.5f, nh));
        float x2 = __fadd_rn(ncx, __fmul_rn(0.5f, nw));
        float y2 = __fadd_rn(ncy, __fmul_rn(0.5f, nh));

        x1 = fminf(fmaxf(x1, 0.0f), W);
        x2 = fminf(fmaxf(x2, 0.0f), W);
        y1 = fminf(fmaxf(y1, 0.0f), H);
        y2 = fminf(fmaxf(y2, 0.0f), H);

        d_topBoxes[bl * PRE_NMS + j] = make_float4(x1, y1, x2, y2);
    }
}

// ---------------------------------------------------------------------------
// Kernel 2: NMS mask — bracket accept, transposed writes, 2 tiles/block. (PDL)
// ---------------------------------------------------------------------------
__global__ __launch_bounds__(128)
void nms_mask_kernel(int blBase) {
    const int bl = blBase + blockIdx.y;
    const int l = bl % NLEV;
    const int N = c_K[l];

    const int grp = threadIdx.x >> 6;
    const int tt  = threadIdx.x & 63;
    const int job = blockIdx.x * MTPB + grp;

    int t = job, y = 0;
    while (t >= NTILE - y) { t -= NTILE - y; ++y; }
    const int x = y + t;

    const int rowStart = y << 6;
    const int colStart = x << 6;
    const bool active = (rowStart < N) && (colStart < N);

    __shared__ float4 cbx[MTPB * 64];
    __shared__ float carea[MTPB * 64];

    grid_dep_wait();

    if (active) {
        int jj = colStart + tt;
        float4 cj = (jj < N) ? d_topBoxes[bl * PRE_NMS + jj] : make_float4(0.f, 0.f, 0.f, 0.f);
        cbx[(grp << 6) + tt] = cj;
        carea[(grp << 6) + tt] = __fmul_rn(fmaxf(__fsub_rn(cj.z, cj.x), 0.0f),
                                           fmaxf(__fsub_rn(cj.w, cj.y), 0.0f));
    }
    __syncthreads();

    if (!active) return;
    const int i = rowStart + tt;
    if (i >= N) return;
    float4 bi = d_topBoxes[bl * PRE_NMS + i];
    float ai = __fmul_rn(fmaxf(__fsub_rn(bi.z, bi.x), 0.0f),
                         fmaxf(__fsub_rn(bi.w, bi.y), 0.0f));
    unsigned long long bits = 0ull;
    #pragma unroll 8
    for (int jl = 0; jl < 64; ++jl) {
        int jg = colStart + jl;
        if (jg <= i || jg >= N) continue;
        float4 bj = cbx[(grp << 6) + jl];
        float xx1 = fmaxf(bi.x, bj.x), yy1 = fmaxf(bi.y, bj.y);
        float xx2 = fminf(bi.z, bj.z), yy2 = fminf(bi.w, bj.w);
        float w = fmaxf(__fsub_rn(xx2, xx1), 0.0f);
        float h = fmaxf(__fsub_rn(yy2, yy1), 0.0f);
        float inter = __fmul_rn(w, h);
        float aj = carea[(grp << 6) + jl];
        float uni = fmaxf(__fsub_rn(__fadd_rn(ai, aj), inter), 1e-9f);
        float tcut = __fmul_rn(0.7f, uni);
        if (inter > __fmul_rn(tcut, 1.00001f)) {
            bits |= (1ull << jl);
        } else if (inter >= __fmul_rn(tcut, 0.99999f)) {
            if (__fdiv_rn(inter, uni) > 0.7f) bits |= (1ull << jl);
        }
    }
    d_maskT[((size_t)bl * 32 + x) * PRE_NMS + i] = bits;
}

// ---------------------------------------------------------------------------
// Kernel 3: pipelined warp-specialized NMS reduce + early-skip. (PDL)
// ---------------------------------------------------------------------------
__global__ __launch_bounds__(1024)
void nms_reduce_kernel(int blBase) {
    grid_dep_wait();
    const int bl = blBase + blockIdx.x;
    const int l = bl % NLEV;
    const int N = c_K[l];
    const int KP = c_KP[l];
    const int tid = threadIdx.x;
    const int warp = tid >> 5;
    const int lane = tid & 31;

    __shared__ unsigned long long s_diag[2048];
    __shared__ unsigned long long s_rem[32];
    __shared__ unsigned long long s_keep[32];
    __shared__ int sA[2048], sB[2048];

    const unsigned long long* mT = d_maskT + (size_t)bl * 32 * PRE_NMS;
    const int NC = (N + 63) >> 6;

    for (int i = tid; i < (NC << 6); i += 1024)
        s_diag[i] = (i < N) ? mT[(size_t)(i >> 6) * PRE_NMS + i] : 0ull;
    if (tid < 32) s_rem[tid] = 0ull;
    __syncthreads();

    unsigned long long kreg = 0ull;

    for (int c = 0; c < NC; ++c) {
        const int cc = c + warp;
        const bool doCol = (c > 0) && (cc < NC);
        unsigned long long m0 = 0ull, m1 = 0ull;
        if (doCol) {
            const int rbase = (c - 1) << 6;
            const unsigned long long* colp = mT + (size_t)cc * PRE_NMS + rbase;
            m0 = colp[lane];
            m1 = colp[32 + lane];
        }
        __syncthreads();

        unsigned long long myContrib = 0ull;
        if (doCol) {
            unsigned long long kprev = (warp == 0) ? kreg : s_keep[c - 1];
            unsigned kl = (unsigned)kprev, kh = (unsigned)(kprev >> 32);
            unsigned long long v = 0ull;
            if ((kl >> lane) & 1u) v |= m0;
            if ((kh >> lane) & 1u) v |= m1;
            unsigned vlo = __reduce_or_sync(0xffffffffu, (unsigned)v);
            unsigned vhi = __reduce_or_sync(0xffffffffu, (unsigned)(v >> 32));
            unsigned long long vv = ((unsigned long long)vhi << 32) | vlo;
            if (warp == 0) myContrib = vv;
            else if (lane == 0) s_rem[cc] |= vv;
        }

        if (warp == 0) {
            unsigned long long rem = s_rem[c] | myContrib;
            unsigned rlo = (unsigned)rem, rhi = (unsigned)(rem >> 32);
            unsigned long long keepw;
            if ((rlo & rhi) == 0xFFFFFFFFu) {
                keepw = 0ull;
            } else {
                unsigned nklo = 0, nkhi = 0;
                const unsigned long long* dg = s_diag + (c << 6);
                #pragma unroll
                for (int k = 0; k < 32; ++k) {
                    unsigned s = (unsigned)((int)(rlo << (31 - k)) >> 31);
                    unsigned long long m = dg[k];
                    rlo |= (unsigned)m & ~s;
                    rhi |= (unsigned)(m >> 32) & ~s;
                    nklo |= ~s & (1u << k);
                }
                #pragma unroll
                for (int k = 0; k < 32; ++k) {
                    unsigned s = (unsigned)((int)(rhi << (31 - k)) >> 31);
                    unsigned long long m = dg[32 + k];
                    rhi |= (unsigned)(m >> 32) & ~s;
                    nkhi |= ~s & (1u << k);
                }
                keepw = ((unsigned long long)nkhi << 32) | nklo;
                const int nr = N - (c << 6);
                if (nr < 64) keepw &= (1ull << nr) - 1ull;
            }
            if (lane == 0) s_keep[c] = keepw;
            kreg = keepw;
        }
    }
    __syncthreads();

    for (int j = tid; j < 2048; j += 1024) {
        int kept = 0;
        if (j < N) kept = (int)((s_keep[j >> 6] >> (j & 63)) & 1ull);
        sA[j] = kept;
    }
    __syncthreads();

    int* src = sA; int* dst = sB;
    for (int off = 1; off < 2048; off <<= 1) {
        for (int j = tid; j < 2048; j += 1024)
            dst[j] = src[j] + ((j >= off) ? src[j - off] : 0);
        __syncthreads();
        int* t = src; src = dst; dst = t;
    }
    const int total = src[2047];

    for (int j = tid; j < N; j += 1024) {
        int kept = (int)((s_keep[j >> 6] >> (j & 63)) & 1ull);
        int incl = src[j];
        if (kept) {
            int rank = incl - 1;
            if (rank < KP) {
                d_lvlScore[bl * POST_NMS + rank] = d_topScore[bl * PRE_NMS + j];
                d_lvlPos  [bl * POST_NMS + rank] = j;
            }
        } else {
            int rank = total + (j - incl);
            if (rank < KP) {
                d_lvlScore[bl * POST_NMS + rank] = -1.0f;
                d_lvlPos  [bl * POST_NMS + rank] = j;
            }
        }
    }
}

// ---------------------------------------------------------------------------
// Kernel 4: final cross-level top-1000 (per-batch; bBase selects chain). (PDL)
// ---------------------------------------------------------------------------
__global__ __launch_bounds__(1024)
void final_kernel(float* __restrict__ out, int bBase) {
    grid_dep_wait();
    const int b = bBase + blockIdx.x;
    const int tid = threadIdx.x;
    __shared__ unsigned long long key[TOTCAT];

    for (int c = tid; c < TOTCAT; c += 1024) {
        int l = (c < 4000) ? (c / 1000) : 4;
        int pos = c - l * 1000;
        float s = d_lvlScore[(b * NLEV + l) * POST_NMS + pos];
        key[c] = ((unsigned long long)ordf(s) << 32) | (unsigned)(~c);
    }
    __syncthreads();

    const int segN[NLEV] = {1000, 1000, 1000, 1000, 768};
    for (int c = tid; c < TOTCAT; c += 1024) {
        unsigned long long ke = key[c];
        int rank = 0;
        #pragma unroll
        for (int l2 = 0; l2 < NLEV; ++l2) {
            const int base2 = l2 * 1000;
            int lo = 0, hi = segN[l2];
            while (lo < hi) {
                int mid = (lo + hi) >> 1;
                if (key[base2 + mid] > ke) lo = mid + 1; else hi = mid;
            }
            rank += lo;
        }
        if (rank < POST_NMS) {
            unsigned hi32 = (unsigned)(ke >> 32);
            int l = (c < 4000) ? (c / 1000) : 4;
            int pos = c - l * 1000;
            float* o = out + ((size_t)b * POST_NMS + rank) * 5;
            o[0] = (float)b;
            if (hi32 & 0x80000000u) {
                int blx = b * NLEV + l;
                int j = d_lvlPos[blx * POST_NMS + pos];
                float4 bx = d_topBoxes[blx * PRE_NMS + j];
                o[1] = bx.x; o[2] = bx.y; o[3] = bx.z; o[4] = bx.w;
            } else {
                o[1] = 0.0f; o[2] = 0.0f; o[3] = 0.0f; o[4] = 0.0f;
            }
        }
    }
}

// ---------------------------------------------------------------------------
// PDL launch helper (stream-aware)
// ---------------------------------------------------------------------------
template <typename F, typename... Args>
static void launch_pdl(cudaStream_t st, dim3 grid, dim3 block, F func, Args... args) {
    cudaLaunchConfig_t cfg = {};
    cfg.gridDim = grid;
    cfg.blockDim = block;
    cfg.dynamicSmemBytes = 0;
    cfg.stream = st;
    cudaLaunchAttribute attr[1];
    attr[0].id = cudaLaunchAttributeProgrammaticStreamSerialization;
    attr[0].val.programmaticStreamSerializationAllowed = 1;
    cfg.attrs = attr;
    cfg.numAttrs = 1;
    cudaLaunchKernelEx(&cfg, func, args...);
}

// One half-chain on stream st: bl in [blBase, blBase+10), batches [bBase, bBase+2)
static void run_chain(cudaStream_t st, int blBase, int bBase,
                      const float* const* probs, const float* const* regs,
                      const float* info, float* out, void* histPtr) {
    cudaMemsetAsync((char*)histPtr + (size_t)blBase * HBINS * sizeof(int), 0,
                    (size_t)NBL_H * HBINS * sizeof(int), st);
    {
        cudaLaunchConfig_t cfg = {};
        cfg.gridDim = dim3(64, NBL_H);
        cfg.blockDim = dim3(256);
        cfg.stream = st;
        cudaLaunchKernelEx(&cfg, hist_kernel,
                           probs[0], probs[1], probs[2], probs[3], probs[4], blBase);
    }
    launch_pdl(st, dim3(NBL_H), dim3(1024), select_kernel, blBase);
    launch_pdl(st, dim3(64, NBL_H), dim3(256), compact_kernel,
               probs[0], probs[1], probs[2], probs[3], probs[4], blBase);
    launch_pdl(st, dim3(NBL_H), dim3(1024), sort_decode_kernel,
               regs[0], regs[1], regs[2], regs[3], regs[4], info, blBase);
    launch_pdl(st, dim3(MGRID, NBL_H), dim3(128), nms_mask_kernel, blBase);
    launch_pdl(st, dim3(NBL_H), dim3(1024), nms_reduce_kernel, blBase);
    launch_pdl(st, dim3(BATCH / 2), dim3(1024), final_kernel, out, bBase);
}

// ---------------------------------------------------------------------------
// Launcher — two independent half-chains (bl 0-9 / bl 10-19) on forked
// streams inside graph capture; fork/join via events.
// ---------------------------------------------------------------------------
extern "C" void kernel_launch(void* const* d_in, const int* in_sizes, int n_in,
                              void* d_out, int out_size) {
    const float* probs[NLEV] = {0, 0, 0, 0, 0};
    const float* regs [NLEV] = {0, 0, 0, 0, 0};
    const float* info = 0;

    for (int i = 0; i < n_in; ++i) {
        const float* p = (const float*)d_in[i];
        switch (in_sizes[i]) {
            case 4 * 196608 * 2: probs[0] = p; break;
            case 4 * 196608 * 4: regs [0] = p; break;
            case 4 * 49152 * 2:  probs[1] = p; break;
            case 4 * 49152 * 4:  regs [1] = p; break;
            case 4 * 12288 * 2:  probs[2] = p; break;
            case 4 * 12288 * 4:  regs [2] = p; break;
            case 4 * 3072 * 2:   probs[3] = p; break;
            case 4 * 3072 * 4:   regs [3] = p; break;
            case 4 * 768 * 2:    probs[4] = p; break;
            case 4 * 768 * 4:    regs [4] = p; break;
            case 12:             info = p; break;
            default: break;
        }
    }
    float* out = (float*)d_out;

    void* histPtr = 0;
    cudaGetSymbolAddress(&histPtr, d_hist);

    cudaStream_t s1;
    cudaEvent_t eFork, eJoin;
    cudaStreamCreateWithFlags(&s1, cudaStreamNonBlocking);
    cudaEventCreateWithFlags(&eFork, cudaEventDisableTiming);
    cudaEventCreateWithFlags(&eJoin, cudaEventDisableTiming);

    // fork: s1 joins the capture graph as a parallel branch
    cudaEventRecord(eFork, 0);
    cudaStreamWaitEvent(s1, eFork, 0);

    run_chain(0,  0,               0,         probs, regs, info, out, histPtr);
    run_chain(s1, NBL_H,           BATCH / 2, probs, regs, info, out, histPtr);

    // join: origin stream waits for s1's branch
    cudaEventRecord(eJoin, s1);
    cudaStreamWaitEvent(0, eJoin, 0);

    cudaEventDestroy(eFork);
    cudaEventDestroy(eJoin);
    cudaStreamDestroy(s1);
}